// round 1
// baseline (speedup 1.0000x reference)
#include <cuda_runtime.h>

// ----------------------------------------------------------------------------
// CrossAttention: fp32 baseline
//   1) qkv_gemm_kernel : x_s @ Wqkv_s -> q,k,v scattered to [s][b][h][n][d]
//   2) attn_kernel     : 4 flash-attention passes (q1k1v1, q1k2v2, q2k2v2, q2k1v1)
//   3) proj_gemm_kernel: (attn_a + attn_b) @ Wp_s + bp_s -> y_s
// ----------------------------------------------------------------------------

#define NB    2
#define NSEQ  1024
#define DIM   768
#define NH    12
#define DH    64
#define QSCALE 0.125f   // 1/sqrt(64)

#define QKV_ELEMS (2*NB*NH*NSEQ*DH)      // 3,145,728 floats per tensor
__device__ float g_q[QKV_ELEMS];
__device__ float g_k[QKV_ELEMS];
__device__ float g_v[QKV_ELEMS];
__device__ float g_attn[4*NB*NSEQ*DIM];  // 4 attention outputs [combo][b][n][h*64+d]

// Fast exp on the FMA/ALU pipes (avoids the slow B300 MUFU path).
// Valid for x <= 0 (softmax domain); ~2e-7 relative accuracy.
__device__ __forceinline__ float fexp(float x) {
    x = fmaxf(x, -87.0f);
    float y = x * 1.4426950408889634f;          // x * log2(e)
    float t = y + 12582912.0f;                   // 1.5 * 2^23 magic round
    int   n = __float_as_int(t) - 0x4B400000;    // round(y) as int
    float f = y - (t - 12582912.0f);             // f in [-0.5, 0.5]
    float p = 1.33335581e-3f;
    p = fmaf(p, f, 9.61812911e-3f);
    p = fmaf(p, f, 5.55041086e-2f);
    p = fmaf(p, f, 2.40226512e-1f);
    p = fmaf(p, f, 6.93147182e-1f);
    p = fmaf(p, f, 1.0f);
    float s = __int_as_float((n + 127) << 23);   // 2^n
    return p * s;
}

// ---------------------------------------------------------------------------
// Kernel 1: QKV GEMM. X[2048x768] @ W[768x2304], scatter epilogue into q/k/v.
// 128x128 tile, BK=8, 256 threads, 8x8 per thread.
// grid = (18, 16, 2)
// ---------------------------------------------------------------------------
__global__ void __launch_bounds__(256) qkv_gemm_kernel(
    const float* __restrict__ X1, const float* __restrict__ X2,
    const float* __restrict__ W1, const float* __restrict__ W2)
{
    const int s = blockIdx.z;
    const float* __restrict__ X = s ? X2 : X1;   // [2048][768]
    const float* __restrict__ W = s ? W2 : W1;   // [768][2304]

    __shared__ float As[8][128];
    __shared__ float Bs[8][128];

    const int tid  = threadIdx.x;
    const int m0   = blockIdx.y * 128;
    const int n0   = blockIdx.x * 128;
    const int arow = tid >> 1, acol = (tid & 1) << 2;
    const int brow = tid >> 5, bcol = (tid & 31) << 2;
    const int tx   = (tid & 15) << 3;
    const int ty   = (tid >> 4) << 3;

    float acc[8][8];
    #pragma unroll
    for (int i = 0; i < 8; i++)
        #pragma unroll
        for (int j = 0; j < 8; j++) acc[i][j] = 0.0f;

    for (int k0 = 0; k0 < DIM; k0 += 8) {
        float4 a4 = *(const float4*)(X + (m0 + arow) * DIM + k0 + acol);
        As[acol + 0][arow] = a4.x;
        As[acol + 1][arow] = a4.y;
        As[acol + 2][arow] = a4.z;
        As[acol + 3][arow] = a4.w;
        *(float4*)(&Bs[brow][bcol]) =
            *(const float4*)(W + (k0 + brow) * (3 * DIM) + n0 + bcol);
        __syncthreads();

        #pragma unroll
        for (int kk = 0; kk < 8; kk++) {
            float ar[8], br[8];
            *(float4*)(ar)     = *(float4*)(&As[kk][ty]);
            *(float4*)(ar + 4) = *(float4*)(&As[kk][ty + 4]);
            *(float4*)(br)     = *(float4*)(&Bs[kk][tx]);
            *(float4*)(br + 4) = *(float4*)(&Bs[kk][tx + 4]);
            #pragma unroll
            for (int i = 0; i < 8; i++)
                #pragma unroll
                for (int j = 0; j < 8; j++)
                    acc[i][j] = fmaf(ar[i], br[j], acc[i][j]);
        }
        __syncthreads();
    }

    // Scatter epilogue: column c -> (t3=q/k/v, h, d); row m -> (b, n)
    #pragma unroll
    for (int j = 0; j < 8; j++) {
        int c   = n0 + tx + j;
        int t3  = c / DIM;            // tile never crosses a 768 boundary (768%128==0)
        int rem = c - t3 * DIM;
        int h   = rem >> 6;
        int d   = rem & 63;
        float* dst = (t3 == 0) ? g_q : (t3 == 1) ? g_k : g_v;
        #pragma unroll
        for (int i = 0; i < 8; i++) {
            int m  = m0 + ty + i;
            int b  = m >> 10;
            int nq = m & (NSEQ - 1);
            dst[(((s * NB + b) * NH + h) * NSEQ + nq) * DH + d] = acc[i][j];
        }
    }
}

// ---------------------------------------------------------------------------
// Kernel 2: flash attention, fp32.
// grid = (8 q-tiles, 24 b*h, 4 combos), 128 threads, 100 KB dynamic smem.
// Per block: Q tile 128 rows, stream over 16 key-tiles of 64, online softmax.
// Thread (rg=t/8, cg=t%8): S tile rows rg*8..+7 x keys cg*8..+7 (8x8 regs),
//                          O tile rows rg*8..+7 x d    cg*8..+7 (8x8 regs).
// ---------------------------------------------------------------------------
#define QS_STRIDE 132
#define KS_STRIDE 68
#define ATTN_SMEM_FLOATS (64*QS_STRIDE + 64*KS_STRIDE + 64*KS_STRIDE + 64*QS_STRIDE)
#define ATTN_SMEM_BYTES  (ATTN_SMEM_FLOATS * 4)   // 102,400 B

__global__ void __launch_bounds__(128, 2) attn_kernel()
{
    extern __shared__ float sm[];
    float* Qs = sm;                          // [64][132]  Qs[d*132 + q]  (transposed, scaled)
    float* Ks = Qs + 64 * QS_STRIDE;         // [64][68]   Ks[d*68 + k]   (transposed)
    float* Vs = Ks + 64 * KS_STRIDE;         // [64][68]   Vs[k*68 + d]
    float* Ps = Vs + 64 * KS_STRIDE;         // [64][132]  Ps[k*132 + q]  (P transposed)

    const int t     = threadIdx.x;
    const int combo = blockIdx.z;            // 0:(q1,kv1) 1:(q1,kv2) 2:(q2,kv2) 3:(q2,kv1)
    const int qs    = combo >> 1;
    const int kvs   = ((combo + 1) >> 1) & 1;
    const int bh    = blockIdx.y;            // b*NH + h
    const int q0    = blockIdx.x * 128;

    const float* __restrict__ Qg = g_q + (qs  * NB * NH + bh) * NSEQ * DH;
    const float* __restrict__ Kg = g_k + (kvs * NB * NH + bh) * NSEQ * DH;
    const float* __restrict__ Vg = g_v + (kvs * NB * NH + bh) * NSEQ * DH;

    // Load Q tile (scaled) transposed into smem: thread t owns q-row q0+t.
    {
        const float* qrow = Qg + (q0 + t) * DH;
        #pragma unroll
        for (int d4 = 0; d4 < DH; d4 += 4) {
            float4 v = *(const float4*)(qrow + d4);
            Qs[(d4 + 0) * QS_STRIDE + t] = v.x * QSCALE;
            Qs[(d4 + 1) * QS_STRIDE + t] = v.y * QSCALE;
            Qs[(d4 + 2) * QS_STRIDE + t] = v.z * QSCALE;
            Qs[(d4 + 3) * QS_STRIDE + t] = v.w * QSCALE;
        }
    }

    const int rg8 = (t >> 3) << 3;   // row base
    const int cg8 = (t & 7) << 3;    // col base (keys in S-phase, d in PV-phase)

    float Ov[64];
    float mrow[8], lrow[8];
    #pragma unroll
    for (int i = 0; i < 64; i++) Ov[i] = 0.0f;
    #pragma unroll
    for (int i = 0; i < 8; i++) { mrow[i] = -1e30f; lrow[i] = 0.0f; }

    const int key   = t >> 1;          // K/V tile staging map
    const int dbase = (t & 1) << 5;

    for (int kt = 0; kt < NSEQ / 64; kt++) {
        const int k0 = kt * 64;
        __syncthreads();   // previous iteration done with Ks/Vs/Ps

        // Stage K (transposed) and V (direct) tiles: 64 keys x 64 d each.
        const float* krow = Kg + (k0 + key) * DH + dbase;
        const float* vrow = Vg + (k0 + key) * DH + dbase;
        #pragma unroll
        for (int dd = 0; dd < 32; dd += 4) {
            float4 k4 = *(const float4*)(krow + dd);
            Ks[(dbase + dd + 0) * KS_STRIDE + key] = k4.x;
            Ks[(dbase + dd + 1) * KS_STRIDE + key] = k4.y;
            Ks[(dbase + dd + 2) * KS_STRIDE + key] = k4.z;
            Ks[(dbase + dd + 3) * KS_STRIDE + key] = k4.w;
            *(float4*)(&Vs[key * KS_STRIDE + dbase + dd]) = *(const float4*)(vrow + dd);
        }
        __syncthreads();

        // S = (Q*scale) . K^T : 8x8 register tile, inner dim 64.
        float Sv[64];
        #pragma unroll
        for (int i = 0; i < 64; i++) Sv[i] = 0.0f;
        #pragma unroll 8
        for (int d = 0; d < DH; d++) {
            float qv[8], kv[8];
            *(float4*)(qv)     = *(const float4*)(&Qs[d * QS_STRIDE + rg8]);
            *(float4*)(qv + 4) = *(const float4*)(&Qs[d * QS_STRIDE + rg8 + 4]);
            *(float4*)(kv)     = *(const float4*)(&Ks[d * KS_STRIDE + cg8]);
            *(float4*)(kv + 4) = *(const float4*)(&Ks[d * KS_STRIDE + cg8 + 4]);
            #pragma unroll
            for (int i = 0; i < 8; i++)
                #pragma unroll
                for (int j = 0; j < 8; j++)
                    Sv[i * 8 + j] = fmaf(qv[i], kv[j], Sv[i * 8 + j]);
        }

        // Online softmax update; rows shared by the 8 consecutive lanes with equal t/8.
        #pragma unroll
        for (int i = 0; i < 8; i++) {
            float mx = Sv[i * 8];
            #pragma unroll
            for (int j = 1; j < 8; j++) mx = fmaxf(mx, Sv[i * 8 + j]);
            mx = fmaxf(mx, __shfl_xor_sync(0xffffffffu, mx, 1));
            mx = fmaxf(mx, __shfl_xor_sync(0xffffffffu, mx, 2));
            mx = fmaxf(mx, __shfl_xor_sync(0xffffffffu, mx, 4));
            float mnew = fmaxf(mrow[i], mx);
            float corr = fexp(mrow[i] - mnew);
            float sum = 0.0f;
            #pragma unroll
            for (int j = 0; j < 8; j++) {
                float p = fexp(Sv[i * 8 + j] - mnew);
                Sv[i * 8 + j] = p;
                sum += p;
            }
            sum += __shfl_xor_sync(0xffffffffu, sum, 1);
            sum += __shfl_xor_sync(0xffffffffu, sum, 2);
            sum += __shfl_xor_sync(0xffffffffu, sum, 4);
            lrow[i] = lrow[i] * corr + sum;
            mrow[i] = mnew;
            #pragma unroll
            for (int j = 0; j < 8; j++) Ov[i * 8 + j] *= corr;
        }

        // Store P transposed (Ps[k][q]) so PV loads are contiguous float4s.
        #pragma unroll
        for (int j = 0; j < 8; j++) {
            int k = cg8 + j;
            float4 p0 = make_float4(Sv[0 * 8 + j], Sv[1 * 8 + j], Sv[2 * 8 + j], Sv[3 * 8 + j]);
            float4 p1 = make_float4(Sv[4 * 8 + j], Sv[5 * 8 + j], Sv[6 * 8 + j], Sv[7 * 8 + j]);
            *(float4*)(&Ps[k * QS_STRIDE + rg8])     = p0;
            *(float4*)(&Ps[k * QS_STRIDE + rg8 + 4]) = p1;
        }
        __syncthreads();

        // O += P . V : 8x8 register tile, inner dim 64 keys.
        #pragma unroll 4
        for (int k = 0; k < 64; k++) {
            float pv[8], vv[8];
            *(float4*)(pv)     = *(const float4*)(&Ps[k * QS_STRIDE + rg8]);
            *(float4*)(pv + 4) = *(const float4*)(&Ps[k * QS_STRIDE + rg8 + 4]);
            *(float4*)(vv)     = *(const float4*)(&Vs[k * KS_STRIDE + cg8]);
            *(float4*)(vv + 4) = *(const float4*)(&Vs[k * KS_STRIDE + cg8 + 4]);
            #pragma unroll
            for (int i = 0; i < 8; i++)
                #pragma unroll
                for (int j = 0; j < 8; j++)
                    Ov[i * 8 + j] = fmaf(pv[i], vv[j], Ov[i * 8 + j]);
        }
    }

    // Normalize and write to g_attn[combo][b][n][h*64 + d]
    const int b = bh / NH, h = bh % NH;
    float* Og = g_attn + ((size_t)(combo * NB + b) * NSEQ + q0) * DIM + h * DH;
    #pragma unroll
    for (int i = 0; i < 8; i++) {
        float inv = 1.0f / lrow[i];
        float4 o0 = make_float4(Ov[i * 8 + 0] * inv, Ov[i * 8 + 1] * inv,
                                Ov[i * 8 + 2] * inv, Ov[i * 8 + 3] * inv);
        float4 o1 = make_float4(Ov[i * 8 + 4] * inv, Ov[i * 8 + 5] * inv,
                                Ov[i * 8 + 6] * inv, Ov[i * 8 + 7] * inv);
        float* orow = Og + (rg8 + i) * DIM + cg8;
        *(float4*)(orow)     = o0;
        *(float4*)(orow + 4) = o1;
    }
}

// ---------------------------------------------------------------------------
// Kernel 3: output projection. (attn_a + attn_b)[2048x768] @ Wp[768x768] + bp.
// grid = (6, 16, 2)
// ---------------------------------------------------------------------------
__global__ void __launch_bounds__(256) proj_gemm_kernel(
    const float* __restrict__ Wp1, const float* __restrict__ bp1,
    const float* __restrict__ Wp2, const float* __restrict__ bp2,
    float* __restrict__ out)
{
    const int s = blockIdx.z;
    const float* __restrict__ A0 = g_attn + (size_t)(2 * s + 0) * (NB * NSEQ * DIM);
    const float* __restrict__ A1 = g_attn + (size_t)(2 * s + 1) * (NB * NSEQ * DIM);
    const float* __restrict__ W    = s ? Wp2 : Wp1;   // [768][768]
    const float* __restrict__ bias = s ? bp2 : bp1;
    float* __restrict__ Y = out + (size_t)s * (NB * NSEQ * DIM);

    __shared__ float As[8][128];
    __shared__ float Bs[8][128];

    const int tid  = threadIdx.x;
    const int m0   = blockIdx.y * 128;
    const int n0   = blockIdx.x * 128;
    const int arow = tid >> 1, acol = (tid & 1) << 2;
    const int brow = tid >> 5, bcol = (tid & 31) << 2;
    const int tx   = (tid & 15) << 3;
    const int ty   = (tid >> 4) << 3;

    float acc[8][8];
    #pragma unroll
    for (int i = 0; i < 8; i++)
        #pragma unroll
        for (int j = 0; j < 8; j++) acc[i][j] = 0.0f;

    for (int k0 = 0; k0 < DIM; k0 += 8) {
        int aidx = (m0 + arow) * DIM + k0 + acol;
        float4 u = *(const float4*)(A0 + aidx);
        float4 w = *(const float4*)(A1 + aidx);
        As[acol + 0][arow] = u.x + w.x;
        As[acol + 1][arow] = u.y + w.y;
        As[acol + 2][arow] = u.z + w.z;
        As[acol + 3][arow] = u.w + w.w;
        *(float4*)(&Bs[brow][bcol]) =
            *(const float4*)(W + (k0 + brow) * DIM + n0 + bcol);
        __syncthreads();

        #pragma unroll
        for (int kk = 0; kk < 8; kk++) {
            float ar[8], br[8];
            *(float4*)(ar)     = *(float4*)(&As[kk][ty]);
            *(float4*)(ar + 4) = *(float4*)(&As[kk][ty + 4]);
            *(float4*)(br)     = *(float4*)(&Bs[kk][tx]);
            *(float4*)(br + 4) = *(float4*)(&Bs[kk][tx + 4]);
            #pragma unroll
            for (int i = 0; i < 8; i++)
                #pragma unroll
                for (int j = 0; j < 8; j++)
                    acc[i][j] = fmaf(ar[i], br[j], acc[i][j]);
        }
        __syncthreads();
    }

    #pragma unroll
    for (int j = 0; j < 8; j++) {
        int c = n0 + tx + j;
        float bb = bias[c];
        #pragma unroll
        for (int i = 0; i < 8; i++) {
            int m = m0 + ty + i;
            Y[(size_t)m * DIM + c] = acc[i][j] + bb;
        }
    }
}

// ---------------------------------------------------------------------------
extern "C" void kernel_launch(void* const* d_in, const int* in_sizes, int n_in,
                              void* d_out, int out_size)
{
    const float* x1    = (const float*)d_in[0];
    const float* x2    = (const float*)d_in[1];
    const float* Wqkv1 = (const float*)d_in[2];
    const float* Wqkv2 = (const float*)d_in[3];
    const float* Wp1   = (const float*)d_in[4];
    const float* bp1   = (const float*)d_in[5];
    const float* Wp2   = (const float*)d_in[6];
    const float* bp2   = (const float*)d_in[7];
    float* out = (float*)d_out;

    cudaFuncSetAttribute(attn_kernel,
                         cudaFuncAttributeMaxDynamicSharedMemorySize,
                         ATTN_SMEM_BYTES);

    qkv_gemm_kernel<<<dim3(18, 16, 2), 256>>>(x1, x2, Wqkv1, Wqkv2);
    attn_kernel<<<dim3(8, 24, 4), 128, ATTN_SMEM_BYTES>>>();
    proj_gemm_kernel<<<dim3(6, 16, 2), 256>>>(Wp1, bp1, Wp2, bp2, out);
}

// round 7
// speedup vs baseline: 1.1063x; 1.1063x over previous
#include <cuda_runtime.h>
#include <cuda_bf16.h>
#include <cstdint>

// ----------------------------------------------------------------------------
// CrossAttention, Round 7:
//   - QKV / projection GEMMs on mma.sync bf16x3-split, with fp32->bf16 hi/lo
//     conversion ON THE FLY in-kernel (no bf16 staging globals, no prep
//     kernels, no cp.async). Total __device__ statics = 62.9MB, identical to
//     the R1 kernel that passed the 128MiB-arena memory guard.
//   - attention unchanged (fp32 SIMT flash attention)
// ----------------------------------------------------------------------------

#define NB    2
#define NSEQ  1024
#define DIM   768
#define NH    12
#define DH    64
#define QSCALE 0.125f

#define MTOT  (NB*NSEQ)        // 2048
#define NQKV  (3*DIM)          // 2304
#define KDIM  DIM              // 768
#define KC    32
#define NCH   (KDIM/KC)        // 24

#define QKV_ELEMS (2*NB*NH*NSEQ*DH)
__device__ float g_q[QKV_ELEMS];
__device__ float g_k[QKV_ELEMS];
__device__ float g_v[QKV_ELEMS];
__device__ float g_attn[4*NB*NSEQ*DIM];
// total statics: 37,748,736 + 25,165,824 = 62,914,560 B  (== Round-1 level)

// ============================ helpers =======================================
// scalar-lvalue MMA macro
#define MMA16816(d0,d1,d2,d3,a0,a1,a2,a3,b0,b1)                               \
    asm volatile(                                                             \
        "mma.sync.aligned.m16n8k16.row.col.f32.bf16.bf16.f32 "                \
        "{%0,%1,%2,%3}, {%4,%5,%6,%7}, {%8,%9}, {%0,%1,%2,%3};"               \
        : "+f"(d0), "+f"(d1), "+f"(d2), "+f"(d3)                              \
        : "r"(a0), "r"(a1), "r"(a2), "r"(a3), "r"(b0), "r"(b1))

__device__ __forceinline__ void split2(float v, __nv_bfloat16& h, __nv_bfloat16& l) {
    h = __float2bfloat16_rn(v);
    l = __float2bfloat16_rn(v - __bfloat162float(h));
}

// ============================ HMMA GEMM =====================================
// C[128m x 64n] per CTA, 256 thr (8 warps, 4x2), warp tile 32x32.
// K in 24 chunks of 32. A fp32 [M][K] (x or attn-sum); B fp32 [K][N] (W).
// In-kernel bf16 hi/lo split; smem K-major tiles; bf16x3:
//   C = Ah*Bh + Ah*Bl + Al*Bh
#define ROWB   80                  // 64 data bytes (32 bf16) + 16 pad
#define OFF_AH 0
#define OFF_AL (128*ROWB)          // 10240
#define OFF_BH (2*128*ROWB)        // 20480
#define OFF_BL (OFF_BH + 64*ROWB)  // 25600
#define STAGEB (OFF_BL + 64*ROWB)  // 30720

#define DECL_ACC(mt,nt) \
    float c##mt##nt##0 = 0.f, c##mt##nt##1 = 0.f, c##mt##nt##2 = 0.f, c##mt##nt##3 = 0.f

#define LDFRAGB(nt) \
    const uint32_t bh##nt##0 = *(const uint32_t*)(bB + (nt)*8*ROWB);              \
    const uint32_t bh##nt##1 = *(const uint32_t*)(bB + (nt)*8*ROWB + 16);         \
    const uint32_t bl##nt##0 = *(const uint32_t*)(bB + (nt)*8*ROWB + 5120);       \
    const uint32_t bl##nt##1 = *(const uint32_t*)(bB + (nt)*8*ROWB + 5120 + 16)

#define MMA3(mt,nt) \
    MMA16816(c##mt##nt##0, c##mt##nt##1, c##mt##nt##2, c##mt##nt##3,          \
             ah0, ah1, ah2, ah3, bh##nt##0, bh##nt##1);                       \
    MMA16816(c##mt##nt##0, c##mt##nt##1, c##mt##nt##2, c##mt##nt##3,          \
             ah0, ah1, ah2, ah3, bl##nt##0, bl##nt##1);                       \
    MMA16816(c##mt##nt##0, c##mt##nt##1, c##mt##nt##2, c##mt##nt##3,          \
             al0, al1, al2, al3, bh##nt##0, bh##nt##1)

#define EPILOG(mt,nt) do {                                                    \
    const int row0 = m0 + wm * 32 + (mt) * 16 + g;                            \
    const int colg = n0 + wn * 32 + (nt) * 8 + 2 * tg;                        \
    const float e0 = c##mt##nt##0, e1 = c##mt##nt##1;                         \
    const float e2 = c##mt##nt##2, e3 = c##mt##nt##3;                         \
    if (mode == 0) {                                                          \
        const int t3  = colg / DIM;                                           \
        const int rem = colg - t3 * DIM;                                      \
        const int h   = rem >> 6;                                             \
        const int d0  = rem & 63;                                             \
        float* dst = (t3 == 0) ? g_q : (t3 == 1) ? g_k : g_v;                 \
        {                                                                     \
            const int m  = row0;                                              \
            const int b_ = m >> 10;                                           \
            const int nq = m & (NSEQ - 1);                                    \
            *(float2*)(dst + ((((size_t)(s * NB + b_) * NH + h) * NSEQ + nq) * DH + d0)) \
                = make_float2(e0, e1);                                        \
        }                                                                     \
        {                                                                     \
            const int m  = row0 + 8;                                          \
            const int b_ = m >> 10;                                           \
            const int nq = m & (NSEQ - 1);                                    \
            *(float2*)(dst + ((((size_t)(s * NB + b_) * NH + h) * NSEQ + nq) * DH + d0)) \
                = make_float2(e2, e3);                                        \
        }                                                                     \
    } else {                                                                  \
        const float* bias = s ? bias2 : bias1;                                \
        const float bx = bias[colg], by = bias[colg + 1];                     \
        *(float2*)(out + ((size_t)s * MTOT + row0) * DIM + colg)              \
            = make_float2(e0 + bx, e1 + by);                                  \
        *(float2*)(out + ((size_t)s * MTOT + row0 + 8) * DIM + colg)          \
            = make_float2(e2 + bx, e3 + by);                                  \
    }                                                                         \
} while (0)

// stage-A global loads for chunk cc into ar[16]
#define STAGE_LOAD_A(cc) do {                                                 \
    const float* _p = pA0 + (cc) * KC;                                        \
    _Pragma("unroll")                                                         \
    for (int i4 = 0; i4 < 4; i4++) {                                          \
        float4 v = *(const float4*)(_p + i4 * 4);                             \
        if (mode == 1) {                                                      \
            float4 w = *(const float4*)(pA1 + (cc) * KC + i4 * 4);            \
            v.x += w.x; v.y += w.y; v.z += w.z; v.w += w.w;                   \
        }                                                                     \
        ar[i4 * 4 + 0] = v.x; ar[i4 * 4 + 1] = v.y;                           \
        ar[i4 * 4 + 2] = v.z; ar[i4 * 4 + 3] = v.w;                           \
    }                                                                         \
} while (0)

// stage-B global loads for chunk cc into br[8] (two k-passes of float4 over n)
#define STAGE_LOAD_B(cc) do {                                                 \
    _Pragma("unroll")                                                         \
    for (int p = 0; p < 2; p++) {                                             \
        float4 v = *(const float4*)(pB + ((size_t)(cc) * KC + p * 16) * Ntot);\
        br[p * 4 + 0] = v.x; br[p * 4 + 1] = v.y;                             \
        br[p * 4 + 2] = v.z; br[p * 4 + 3] = v.w;                             \
    }                                                                         \
} while (0)

__global__ void __launch_bounds__(256, 1) hmma_gemm_kernel(
    const float* __restrict__ A1g, const float* __restrict__ A2g,
    const float* __restrict__ B1g, const float* __restrict__ B2g,
    int Ntot, int mode,
    const float* __restrict__ bias1, const float* __restrict__ bias2,
    float* __restrict__ out)
{
    __shared__ __align__(16) char smc[STAGEB];
    const int tid  = threadIdx.x;
    const int lane = tid & 31;
    const int warp = tid >> 5;
    const int wm   = warp >> 1;        // 0..3
    const int wn   = warp & 1;         // 0..1
    const int g    = lane >> 2;        // 0..7
    const int tg   = lane & 3;         // 0..3
    const int s    = blockIdx.z;
    const int m0   = blockIdx.y * 128;
    const int n0   = blockIdx.x * 64;

    // A staging map: 2 threads per row, 16 k-floats each
    const int arow = tid >> 1;            // 0..127
    const int akb  = (tid & 1) * 16;      // 0 or 16
    const float* pA0;
    const float* pA1 = nullptr;
    if (mode == 0) {
        const float* Ag = s ? A2g : A1g;  // x [2048][768]
        pA0 = Ag + (size_t)(m0 + arow) * KDIM + akb;
    } else {
        const size_t per = (size_t)MTOT * KDIM;
        pA0 = g_attn + (size_t)(2 * s) * per + (size_t)(m0 + arow) * KDIM + akb;
        pA1 = pA0 + per;
    }

    // B staging map: W [768][Ntot]; thread reads float4 along n at k-row kkB
    const float* Bg = s ? B2g : B1g;
    const int kkB = tid >> 4;             // 0..15 (plus p*16)
    const int nnB = (tid & 15) * 4;       // 0..60
    const float* pB = Bg + (size_t)kkB * Ntot + n0 + nnB;

    DECL_ACC(0,0); DECL_ACC(0,1); DECL_ACC(0,2); DECL_ACC(0,3);
    DECL_ACC(1,0); DECL_ACC(1,1); DECL_ACC(1,2); DECL_ACC(1,3);

    float ar[16];
    float br[8];
    STAGE_LOAD_A(0);
    STAGE_LOAD_B(0);

    for (int c = 0; c < NCH; c++) {
        // ---- convert & store staged chunk to smem ----
        {
            char* adst = smc + arow * ROWB + akb * 2;   // bf16: k elem -> 2B
            #pragma unroll
            for (int i = 0; i < 8; i++) {
                __nv_bfloat16 h0, l0, h1, l1;
                split2(ar[2 * i],     h0, l0);
                split2(ar[2 * i + 1], h1, l1);
                __nv_bfloat162 th; th.x = h0; th.y = h1;
                __nv_bfloat162 tl; tl.x = l0; tl.y = l1;
                *(__nv_bfloat162*)(adst + OFF_AH + i * 4) = th;
                *(__nv_bfloat162*)(adst + OFF_AL + i * 4) = tl;
            }
            #pragma unroll
            for (int p = 0; p < 2; p++) {
                const int kchunk = kkB + p * 16;
                #pragma unroll
                for (int j = 0; j < 4; j++) {
                    __nv_bfloat16 h, l;
                    split2(br[p * 4 + j], h, l);
                    const int n = nnB + j;
                    *(__nv_bfloat16*)(smc + OFF_BH + n * ROWB + kchunk * 2) = h;
                    *(__nv_bfloat16*)(smc + OFF_BL + n * ROWB + kchunk * 2) = l;
                }
            }
        }
        __syncthreads();

        // ---- prefetch next chunk (LDG latency hides under MMAs) ----
        if (c + 1 < NCH) {
            STAGE_LOAD_A(c + 1);
            STAGE_LOAD_B(c + 1);
        }

        // ---- MMAs on smem ----
        #pragma unroll
        for (int kk = 0; kk < 2; kk++) {
            const int kof = kk * 32 + tg * 4;
            const char* bB = smc + OFF_BH + (wn * 32 + g) * ROWB + kof;
            LDFRAGB(0); LDFRAGB(1); LDFRAGB(2); LDFRAGB(3);
            {   // mt = 0
                const char* aP = smc + (wm * 32 + g) * ROWB + kof;
                const uint32_t ah0 = *(const uint32_t*)(aP + OFF_AH);
                const uint32_t ah1 = *(const uint32_t*)(aP + OFF_AH + 8 * ROWB);
                const uint32_t ah2 = *(const uint32_t*)(aP + OFF_AH + 16);
                const uint32_t ah3 = *(const uint32_t*)(aP + OFF_AH + 8 * ROWB + 16);
                const uint32_t al0 = *(const uint32_t*)(aP + OFF_AL);
                const uint32_t al1 = *(const uint32_t*)(aP + OFF_AL + 8 * ROWB);
                const uint32_t al2 = *(const uint32_t*)(aP + OFF_AL + 16);
                const uint32_t al3 = *(const uint32_t*)(aP + OFF_AL + 8 * ROWB + 16);
                MMA3(0,0); MMA3(0,1); MMA3(0,2); MMA3(0,3);
            }
            {   // mt = 1
                const char* aP = smc + (wm * 32 + 16 + g) * ROWB + kof;
                const uint32_t ah0 = *(const uint32_t*)(aP + OFF_AH);
                const uint32_t ah1 = *(const uint32_t*)(aP + OFF_AH + 8 * ROWB);
                const uint32_t ah2 = *(const uint32_t*)(aP + OFF_AH + 16);
                const uint32_t ah3 = *(const uint32_t*)(aP + OFF_AH + 8 * ROWB + 16);
                const uint32_t al0 = *(const uint32_t*)(aP + OFF_AL);
                const uint32_t al1 = *(const uint32_t*)(aP + OFF_AL + 8 * ROWB);
                const uint32_t al2 = *(const uint32_t*)(aP + OFF_AL + 16);
                const uint32_t al3 = *(const uint32_t*)(aP + OFF_AL + 8 * ROWB + 16);
                MMA3(1,0); MMA3(1,1); MMA3(1,2); MMA3(1,3);
            }
        }
        __syncthreads();
    }

    EPILOG(0,0); EPILOG(0,1); EPILOG(0,2); EPILOG(0,3);
    EPILOG(1,0); EPILOG(1,1); EPILOG(1,2); EPILOG(1,3);
}

// ============================ attention (unchanged) =========================
__device__ __forceinline__ float fexp(float x) {
    x = fmaxf(x, -87.0f);
    float y = x * 1.4426950408889634f;
    float t = y + 12582912.0f;
    int   n = __float_as_int(t) - 0x4B400000;
    float f = y - (t - 12582912.0f);
    float p = 1.33335581e-3f;
    p = fmaf(p, f, 9.61812911e-3f);
    p = fmaf(p, f, 5.55041086e-2f);
    p = fmaf(p, f, 2.40226512e-1f);
    p = fmaf(p, f, 6.93147182e-1f);
    p = fmaf(p, f, 1.0f);
    float s = __int_as_float((n + 127) << 23);
    return p * s;
}

#define QS_STRIDE 132
#define KS_STRIDE 68
#define ATTN_SMEM_FLOATS (64*QS_STRIDE + 64*KS_STRIDE + 64*KS_STRIDE + 64*QS_STRIDE)
#define ATTN_SMEM_BYTES  (ATTN_SMEM_FLOATS * 4)

__global__ void __launch_bounds__(128, 2) attn_kernel()
{
    extern __shared__ float smf[];
    float* Qs = smf;
    float* Ks = Qs + 64 * QS_STRIDE;
    float* Vs = Ks + 64 * KS_STRIDE;
    float* Ps = Vs + 64 * KS_STRIDE;

    const int t     = threadIdx.x;
    const int combo = blockIdx.z;
    const int qs    = combo >> 1;
    const int kvs   = ((combo + 1) >> 1) & 1;
    const int bh    = blockIdx.y;
    const int q0    = blockIdx.x * 128;

    const float* __restrict__ Qg = g_q + (qs  * NB * NH + bh) * NSEQ * DH;
    const float* __restrict__ Kg = g_k + (kvs * NB * NH + bh) * NSEQ * DH;
    const float* __restrict__ Vg = g_v + (kvs * NB * NH + bh) * NSEQ * DH;

    {
        const float* qrow = Qg + (q0 + t) * DH;
        #pragma unroll
        for (int d4 = 0; d4 < DH; d4 += 4) {
            float4 v = *(const float4*)(qrow + d4);
            Qs[(d4 + 0) * QS_STRIDE + t] = v.x * QSCALE;
            Qs[(d4 + 1) * QS_STRIDE + t] = v.y * QSCALE;
            Qs[(d4 + 2) * QS_STRIDE + t] = v.z * QSCALE;
            Qs[(d4 + 3) * QS_STRIDE + t] = v.w * QSCALE;
        }
    }

    const int rg8 = (t >> 3) << 3;
    const int cg8 = (t & 7) << 3;

    float Ov[64];
    float mrow[8], lrow[8];
    #pragma unroll
    for (int i = 0; i < 64; i++) Ov[i] = 0.0f;
    #pragma unroll
    for (int i = 0; i < 8; i++) { mrow[i] = -1e30f; lrow[i] = 0.0f; }

    const int key   = t >> 1;
    const int dbase = (t & 1) << 5;

    for (int kt = 0; kt < NSEQ / 64; kt++) {
        const int k0 = kt * 64;
        __syncthreads();

        const float* krow = Kg + (k0 + key) * DH + dbase;
        const float* vrow = Vg + (k0 + key) * DH + dbase;
        #pragma unroll
        for (int dd = 0; dd < 32; dd += 4) {
            float4 k4 = *(const float4*)(krow + dd);
            Ks[(dbase + dd + 0) * KS_STRIDE + key] = k4.x;
            Ks[(dbase + dd + 1) * KS_STRIDE + key] = k4.y;
            Ks[(dbase + dd + 2) * KS_STRIDE + key] = k4.z;
            Ks[(dbase + dd + 3) * KS_STRIDE + key] = k4.w;
            *(float4*)(&Vs[key * KS_STRIDE + dbase + dd]) = *(const float4*)(vrow + dd);
        }
        __syncthreads();

        float Sv[64];
        #pragma unroll
        for (int i = 0; i < 64; i++) Sv[i] = 0.0f;
        #pragma unroll 8
        for (int d = 0; d < DH; d++) {
            float qv[8], kv[8];
            *(float4*)(qv)     = *(const float4*)(&Qs[d * QS_STRIDE + rg8]);
            *(float4*)(qv + 4) = *(const float4*)(&Qs[d * QS_STRIDE + rg8 + 4]);
            *(float4*)(kv)     = *(const float4*)(&Ks[d * KS_STRIDE + cg8]);
            *(float4*)(kv + 4) = *(const float4*)(&Ks[d * KS_STRIDE + cg8 + 4]);
            #pragma unroll
            for (int i = 0; i < 8; i++)
                #pragma unroll
                for (int j = 0; j < 8; j++)
                    Sv[i * 8 + j] = fmaf(qv[i], kv[j], Sv[i * 8 + j]);
        }

        #pragma unroll
        for (int i = 0; i < 8; i++) {
            float mx = Sv[i * 8];
            #pragma unroll
            for (int j = 1; j < 8; j++) mx = fmaxf(mx, Sv[i * 8 + j]);
            mx = fmaxf(mx, __shfl_xor_sync(0xffffffffu, mx, 1));
            mx = fmaxf(mx, __shfl_xor_sync(0xffffffffu, mx, 2));
            mx = fmaxf(mx, __shfl_xor_sync(0xffffffffu, mx, 4));
            float mnew = fmaxf(mrow[i], mx);
            float corr = fexp(mrow[i] - mnew);
            float sum = 0.0f;
            #pragma unroll
            for (int j = 0; j < 8; j++) {
                float p = fexp(Sv[i * 8 + j] - mnew);
                Sv[i * 8 + j] = p;
                sum += p;
            }
            sum += __shfl_xor_sync(0xffffffffu, sum, 1);
            sum += __shfl_xor_sync(0xffffffffu, sum, 2);
            sum += __shfl_xor_sync(0xffffffffu, sum, 4);
            lrow[i] = lrow[i] * corr + sum;
            mrow[i] = mnew;
            #pragma unroll
            for (int j = 0; j < 8; j++) Ov[i * 8 + j] *= corr;
        }

        #pragma unroll
        for (int j = 0; j < 8; j++) {
            int k = cg8 + j;
            float4 p0 = make_float4(Sv[0 * 8 + j], Sv[1 * 8 + j], Sv[2 * 8 + j], Sv[3 * 8 + j]);
            float4 p1 = make_float4(Sv[4 * 8 + j], Sv[5 * 8 + j], Sv[6 * 8 + j], Sv[7 * 8 + j]);
            *(float4*)(&Ps[k * QS_STRIDE + rg8])     = p0;
            *(float4*)(&Ps[k * QS_STRIDE + rg8 + 4]) = p1;
        }
        __syncthreads();

        #pragma unroll 4
        for (int k = 0; k < 64; k++) {
            float pv[8], vv[8];
            *(float4*)(pv)     = *(const float4*)(&Ps[k * QS_STRIDE + rg8]);
            *(float4*)(pv + 4) = *(const float4*)(&Ps[k * QS_STRIDE + rg8 + 4]);
            *(float4*)(vv)     = *(const float4*)(&Vs[k * KS_STRIDE + cg8]);
            *(float4*)(vv + 4) = *(const float4*)(&Vs[k * KS_STRIDE + cg8 + 4]);
            #pragma unroll
            for (int i = 0; i < 8; i++)
                #pragma unroll
                for (int j = 0; j < 8; j++)
                    Ov[i * 8 + j] = fmaf(pv[i], vv[j], Ov[i * 8 + j]);
        }
    }

    const int b = bh / NH, h = bh % NH;
    float* Og = g_attn + ((size_t)(combo * NB + b) * NSEQ + q0) * DIM + h * DH;
    #pragma unroll
    for (int i = 0; i < 8; i++) {
        float inv = 1.0f / lrow[i];
        float4 o0 = make_float4(Ov[i * 8 + 0] * inv, Ov[i * 8 + 1] * inv,
                                Ov[i * 8 + 2] * inv, Ov[i * 8 + 3] * inv);
        float4 o1 = make_float4(Ov[i * 8 + 4] * inv, Ov[i * 8 + 5] * inv,
                                Ov[i * 8 + 6] * inv, Ov[i * 8 + 7] * inv);
        float* orow = Og + (rg8 + i) * DIM + cg8;
        *(float4*)(orow)     = o0;
        *(float4*)(orow + 4) = o1;
    }
}

// ============================ launch ========================================
extern "C" void kernel_launch(void* const* d_in, const int* in_sizes, int n_in,
                              void* d_out, int out_size)
{
    const float* x1    = (const float*)d_in[0];
    const float* x2    = (const float*)d_in[1];
    const float* Wqkv1 = (const float*)d_in[2];
    const float* Wqkv2 = (const float*)d_in[3];
    const float* Wp1   = (const float*)d_in[4];
    const float* bp1   = (const float*)d_in[5];
    const float* Wp2   = (const float*)d_in[6];
    const float* bp2   = (const float*)d_in[7];
    float* out = (float*)d_out;

    cudaFuncSetAttribute(attn_kernel,
                         cudaFuncAttributeMaxDynamicSharedMemorySize, ATTN_SMEM_BYTES);

    // QKV: C[2048 x 2304] per stream
    hmma_gemm_kernel<<<dim3(NQKV / 64, MTOT / 128, 2), 256>>>(
        x1, x2, Wqkv1, Wqkv2, NQKV, 0, nullptr, nullptr, nullptr);

    attn_kernel<<<dim3(8, 24, 4), 128, ATTN_SMEM_BYTES>>>();

    // proj: C[2048 x 768] per stream, A = attn combo sums (computed in-kernel)
    hmma_gemm_kernel<<<dim3(DIM / 64, MTOT / 128, 2), 256>>>(
        nullptr, nullptr, Wp1, Wp2, DIM, 1, bp1, bp2, out);
}

// round 8
// speedup vs baseline: 1.7837x; 1.6123x over previous
#include <cuda_runtime.h>
#include <cuda_bf16.h>
#include <cstdint>

// ----------------------------------------------------------------------------
// CrossAttention, Round 8:
//   - QKV / projection GEMMs: unchanged from R7 (in-kernel bf16x3 HMMA),
//     except V is now stored TRANSPOSED (d-major) by the QKV epilogue.
//   - attention: NEW tensor-core flash attention (bf16x3 split QK^T and PV,
//     P repacked register-to-register into A-fragments, online softmax).
//   Statics = 62.9MB (same as R1/R7; inside the proven memory-arena budget).
// ----------------------------------------------------------------------------

#define NB    2
#define NSEQ  1024
#define DIM   768
#define NH    12
#define DH    64
#define QSCALE 0.125f

#define MTOT  (NB*NSEQ)        // 2048
#define NQKV  (3*DIM)          // 2304
#define KDIM  DIM              // 768
#define KC    32
#define NCH   (KDIM/KC)        // 24

#define QKV_ELEMS (2*NB*NH*NSEQ*DH)
__device__ float g_q[QKV_ELEMS];           // [s][b][h][n][d]
__device__ float g_k[QKV_ELEMS];           // [s][b][h][n][d]
__device__ float g_v[QKV_ELEMS];           // [s][b][h][d][n]  (TRANSPOSED)
__device__ float g_attn[4*NB*NSEQ*DIM];

// ============================ helpers =======================================
#define MMA16816(d0,d1,d2,d3,a0,a1,a2,a3,b0,b1)                               \
    asm volatile(                                                             \
        "mma.sync.aligned.m16n8k16.row.col.f32.bf16.bf16.f32 "                \
        "{%0,%1,%2,%3}, {%4,%5,%6,%7}, {%8,%9}, {%0,%1,%2,%3};"               \
        : "+f"(d0), "+f"(d1), "+f"(d2), "+f"(d3)                              \
        : "r"(a0), "r"(a1), "r"(a2), "r"(a3), "r"(b0), "r"(b1))

__device__ __forceinline__ void split2(float v, __nv_bfloat16& h, __nv_bfloat16& l) {
    h = __float2bfloat16_rn(v);
    l = __float2bfloat16_rn(v - __bfloat162float(h));
}

// split two floats -> packed bf16x2 hi + packed bf16x2 lo
__device__ __forceinline__ void splitpack2(float x, float y,
                                           uint32_t& hp, uint32_t& lp) {
    __nv_bfloat16 hx = __float2bfloat16_rn(x);
    __nv_bfloat16 hy = __float2bfloat16_rn(y);
    __nv_bfloat16 lx = __float2bfloat16_rn(x - __bfloat162float(hx));
    __nv_bfloat16 ly = __float2bfloat16_rn(y - __bfloat162float(hy));
    hp = (uint32_t)__bfloat16_as_ushort(hx) | ((uint32_t)__bfloat16_as_ushort(hy) << 16);
    lp = (uint32_t)__bfloat16_as_ushort(lx) | ((uint32_t)__bfloat16_as_ushort(ly) << 16);
}

__device__ __forceinline__ float fexp(float x) {
    x = fmaxf(x, -87.0f);
    float y = x * 1.4426950408889634f;
    float t = y + 12582912.0f;
    int   n = __float_as_int(t) - 0x4B400000;
    float f = y - (t - 12582912.0f);
    float p = 1.33335581e-3f;
    p = fmaf(p, f, 9.61812911e-3f);
    p = fmaf(p, f, 5.55041086e-2f);
    p = fmaf(p, f, 2.40226512e-1f);
    p = fmaf(p, f, 6.93147182e-1f);
    p = fmaf(p, f, 1.0f);
    float s = __int_as_float((n + 127) << 23);
    return p * s;
}

// ============================ HMMA GEMM (R7, V-transposed epilogue) =========
#define ROWB   80
#define OFF_AH 0
#define OFF_AL (128*ROWB)
#define OFF_BH (2*128*ROWB)
#define OFF_BL (OFF_BH + 64*ROWB)
#define STAGEB (OFF_BL + 64*ROWB)  // 30720

#define DECL_ACC(mt,nt) \
    float c##mt##nt##0 = 0.f, c##mt##nt##1 = 0.f, c##mt##nt##2 = 0.f, c##mt##nt##3 = 0.f

#define LDFRAGB(nt) \
    const uint32_t bh##nt##0 = *(const uint32_t*)(bB + (nt)*8*ROWB);              \
    const uint32_t bh##nt##1 = *(const uint32_t*)(bB + (nt)*8*ROWB + 16);         \
    const uint32_t bl##nt##0 = *(const uint32_t*)(bB + (nt)*8*ROWB + 5120);       \
    const uint32_t bl##nt##1 = *(const uint32_t*)(bB + (nt)*8*ROWB + 5120 + 16)

#define MMA3(mt,nt) \
    MMA16816(c##mt##nt##0, c##mt##nt##1, c##mt##nt##2, c##mt##nt##3,          \
             ah0, ah1, ah2, ah3, bh##nt##0, bh##nt##1);                       \
    MMA16816(c##mt##nt##0, c##mt##nt##1, c##mt##nt##2, c##mt##nt##3,          \
             ah0, ah1, ah2, ah3, bl##nt##0, bl##nt##1);                       \
    MMA16816(c##mt##nt##0, c##mt##nt##1, c##mt##nt##2, c##mt##nt##3,          \
             al0, al1, al2, al3, bh##nt##0, bh##nt##1)

#define EPILOG(mt,nt) do {                                                    \
    const int row0 = m0 + wm * 32 + (mt) * 16 + g;                            \
    const int colg = n0 + wn * 32 + (nt) * 8 + 2 * tg;                        \
    const float e0 = c##mt##nt##0, e1 = c##mt##nt##1;                         \
    const float e2 = c##mt##nt##2, e3 = c##mt##nt##3;                         \
    if (mode == 0) {                                                          \
        const int t3  = colg / DIM;                                           \
        const int rem = colg - t3 * DIM;                                      \
        const int h   = rem >> 6;                                             \
        const int d0  = rem & 63;                                             \
        const int m1_ = row0,     b1_ = m1_ >> 10, nq1 = m1_ & (NSEQ - 1);    \
        const int m2_ = row0 + 8, b2_ = m2_ >> 10, nq2 = m2_ & (NSEQ - 1);    \
        if (t3 == 2) {                                                        \
            const size_t vb1 = (((size_t)(s * NB + b1_) * NH + h) * DH + d0) * NSEQ + nq1; \
            const size_t vb2 = (((size_t)(s * NB + b2_) * NH + h) * DH + d0) * NSEQ + nq2; \
            g_v[vb1] = e0; g_v[vb1 + NSEQ] = e1;                              \
            g_v[vb2] = e2; g_v[vb2 + NSEQ] = e3;                              \
        } else {                                                              \
            float* dst = (t3 == 0) ? g_q : g_k;                               \
            *(float2*)(dst + ((((size_t)(s * NB + b1_) * NH + h) * NSEQ + nq1) * DH + d0)) \
                = make_float2(e0, e1);                                        \
            *(float2*)(dst + ((((size_t)(s * NB + b2_) * NH + h) * NSEQ + nq2) * DH + d0)) \
                = make_float2(e2, e3);                                        \
        }                                                                     \
    } else {                                                                  \
        const float* bias = s ? bias2 : bias1;                                \
        const float bx = bias[colg], by = bias[colg + 1];                     \
        *(float2*)(out + ((size_t)s * MTOT + row0) * DIM + colg)              \
            = make_float2(e0 + bx, e1 + by);                                  \
        *(float2*)(out + ((size_t)s * MTOT + row0 + 8) * DIM + colg)          \
            = make_float2(e2 + bx, e3 + by);                                  \
    }                                                                         \
} while (0)

#define STAGE_LOAD_A(cc) do {                                                 \
    const float* _p = pA0 + (cc) * KC;                                        \
    _Pragma("unroll")                                                         \
    for (int i4 = 0; i4 < 4; i4++) {                                          \
        float4 v = *(const float4*)(_p + i4 * 4);                             \
        if (mode == 1) {                                                      \
            float4 w = *(const float4*)(pA1 + (cc) * KC + i4 * 4);            \
            v.x += w.x; v.y += w.y; v.z += w.z; v.w += w.w;                   \
        }                                                                     \
        ar[i4 * 4 + 0] = v.x; ar[i4 * 4 + 1] = v.y;                           \
        ar[i4 * 4 + 2] = v.z; ar[i4 * 4 + 3] = v.w;                           \
    }                                                                         \
} while (0)

#define STAGE_LOAD_B(cc) do {                                                 \
    _Pragma("unroll")                                                         \
    for (int p = 0; p < 2; p++) {                                             \
        float4 v = *(const float4*)(pB + ((size_t)(cc) * KC + p * 16) * Ntot);\
        br[p * 4 + 0] = v.x; br[p * 4 + 1] = v.y;                             \
        br[p * 4 + 2] = v.z; br[p * 4 + 3] = v.w;                             \
    }                                                                         \
} while (0)

__global__ void __launch_bounds__(256, 1) hmma_gemm_kernel(
    const float* __restrict__ A1g, const float* __restrict__ A2g,
    const float* __restrict__ B1g, const float* __restrict__ B2g,
    int Ntot, int mode,
    const float* __restrict__ bias1, const float* __restrict__ bias2,
    float* __restrict__ out)
{
    __shared__ __align__(16) char smc[STAGEB];
    const int tid  = threadIdx.x;
    const int lane = tid & 31;
    const int warp = tid >> 5;
    const int wm   = warp >> 1;
    const int wn   = warp & 1;
    const int g    = lane >> 2;
    const int tg   = lane & 3;
    const int s    = blockIdx.z;
    const int m0   = blockIdx.y * 128;
    const int n0   = blockIdx.x * 64;

    const int arow = tid >> 1;
    const int akb  = (tid & 1) * 16;
    const float* pA0;
    const float* pA1 = nullptr;
    if (mode == 0) {
        const float* Ag = s ? A2g : A1g;
        pA0 = Ag + (size_t)(m0 + arow) * KDIM + akb;
    } else {
        const size_t per = (size_t)MTOT * KDIM;
        pA0 = g_attn + (size_t)(2 * s) * per + (size_t)(m0 + arow) * KDIM + akb;
        pA1 = pA0 + per;
    }

    const float* Bg = s ? B2g : B1g;
    const int kkB = tid >> 4;
    const int nnB = (tid & 15) * 4;
    const float* pB = Bg + (size_t)kkB * Ntot + n0 + nnB;

    DECL_ACC(0,0); DECL_ACC(0,1); DECL_ACC(0,2); DECL_ACC(0,3);
    DECL_ACC(1,0); DECL_ACC(1,1); DECL_ACC(1,2); DECL_ACC(1,3);

    float ar[16];
    float br[8];
    STAGE_LOAD_A(0);
    STAGE_LOAD_B(0);

    for (int c = 0; c < NCH; c++) {
        {
            char* adst = smc + arow * ROWB + akb * 2;
            #pragma unroll
            for (int i = 0; i < 8; i++) {
                uint32_t hp, lp;
                splitpack2(ar[2 * i], ar[2 * i + 1], hp, lp);
                *(uint32_t*)(adst + OFF_AH + i * 4) = hp;
                *(uint32_t*)(adst + OFF_AL + i * 4) = lp;
            }
            #pragma unroll
            for (int p = 0; p < 2; p++) {
                const int kchunk = kkB + p * 16;
                #pragma unroll
                for (int j = 0; j < 4; j++) {
                    __nv_bfloat16 h, l;
                    split2(br[p * 4 + j], h, l);
                    const int n = nnB + j;
                    *(__nv_bfloat16*)(smc + OFF_BH + n * ROWB + kchunk * 2) = h;
                    *(__nv_bfloat16*)(smc + OFF_BL + n * ROWB + kchunk * 2) = l;
                }
            }
        }
        __syncthreads();

        if (c + 1 < NCH) {
            STAGE_LOAD_A(c + 1);
            STAGE_LOAD_B(c + 1);
        }

        #pragma unroll
        for (int kk = 0; kk < 2; kk++) {
            const int kof = kk * 32 + tg * 4;
            const char* bB = smc + OFF_BH + (wn * 32 + g) * ROWB + kof;
            LDFRAGB(0); LDFRAGB(1); LDFRAGB(2); LDFRAGB(3);
            {
                const char* aP = smc + (wm * 32 + g) * ROWB + kof;
                const uint32_t ah0 = *(const uint32_t*)(aP + OFF_AH);
                const uint32_t ah1 = *(const uint32_t*)(aP + OFF_AH + 8 * ROWB);
                const uint32_t ah2 = *(const uint32_t*)(aP + OFF_AH + 16);
                const uint32_t ah3 = *(const uint32_t*)(aP + OFF_AH + 8 * ROWB + 16);
                const uint32_t al0 = *(const uint32_t*)(aP + OFF_AL);
                const uint32_t al1 = *(const uint32_t*)(aP + OFF_AL + 8 * ROWB);
                const uint32_t al2 = *(const uint32_t*)(aP + OFF_AL + 16);
                const uint32_t al3 = *(const uint32_t*)(aP + OFF_AL + 8 * ROWB + 16);
                MMA3(0,0); MMA3(0,1); MMA3(0,2); MMA3(0,3);
            }
            {
                const char* aP = smc + (wm * 32 + 16 + g) * ROWB + kof;
                const uint32_t ah0 = *(const uint32_t*)(aP + OFF_AH);
                const uint32_t ah1 = *(const uint32_t*)(aP + OFF_AH + 8 * ROWB);
                const uint32_t ah2 = *(const uint32_t*)(aP + OFF_AH + 16);
                const uint32_t ah3 = *(const uint32_t*)(aP + OFF_AH + 8 * ROWB + 16);
                const uint32_t al0 = *(const uint32_t*)(aP + OFF_AL);
                const uint32_t al1 = *(const uint32_t*)(aP + OFF_AL + 8 * ROWB);
                const uint32_t al2 = *(const uint32_t*)(aP + OFF_AL + 16);
                const uint32_t al3 = *(const uint32_t*)(aP + OFF_AL + 8 * ROWB + 16);
                MMA3(1,0); MMA3(1,1); MMA3(1,2); MMA3(1,3);
            }
        }
        __syncthreads();
    }

    EPILOG(0,0); EPILOG(0,1); EPILOG(0,2); EPILOG(0,3);
    EPILOG(1,0); EPILOG(1,1); EPILOG(1,2); EPILOG(1,3);
}

// ============================ HMMA attention ================================
// grid (8 qtiles, 24 bh, 4 combos), 256 thr (8 warps x 16 q-rows).
// Per key-tile (64 keys): stage K[key][d] and V[d][key] bf16 hi/lo in smem,
// S = QK^T (3-MMA split, Q frags in regs), online softmax on C-frags,
// P repacked in-register to A-frags, O += PV (3-MMA split).
#define AROWB  144                  // 64 x 2B + 16 pad
#define A_VOFF (2*64*AROWB)         // 18432 (V region)
#define A_LOFF (64*AROWB)           // 9216  (hi->lo offset)
#define ATT_SMEM (4*64*AROWB)       // 36864

#define LOADQ(ks)                                                             \
    uint32_t qh##ks##0, qh##ks##1, qh##ks##2, qh##ks##3;                      \
    uint32_t ql##ks##0, ql##ks##1, ql##ks##2, ql##ks##3;                      \
    do {                                                                      \
        const float2 fa = *(const float2*)(Qrow0 + (ks)*16 + 2*tg);           \
        const float2 fb = *(const float2*)(Qrow1 + (ks)*16 + 2*tg);           \
        const float2 fc = *(const float2*)(Qrow0 + (ks)*16 + 8 + 2*tg);       \
        const float2 fd = *(const float2*)(Qrow1 + (ks)*16 + 8 + 2*tg);       \
        splitpack2(fa.x*QSCALE, fa.y*QSCALE, qh##ks##0, ql##ks##0);           \
        splitpack2(fb.x*QSCALE, fb.y*QSCALE, qh##ks##1, ql##ks##1);           \
        splitpack2(fc.x*QSCALE, fc.y*QSCALE, qh##ks##2, ql##ks##2);           \
        splitpack2(fd.x*QSCALE, fd.y*QSCALE, qh##ks##3, ql##ks##3);           \
    } while (0)

#define ADECL_S(nt) float s##nt##0=0.f, s##nt##1=0.f, s##nt##2=0.f, s##nt##3=0.f
#define ADECL_O(nt) float o##nt##0=0.f, o##nt##1=0.f, o##nt##2=0.f, o##nt##3=0.f
#define ADECL_P(nt) uint32_t pha##nt=0u, phb##nt=0u, pla##nt=0u, plb##nt=0u

#define ASMMA(ks,nt) do {                                                     \
    const char* kb_ = smc + ((nt)*8+g)*AROWB + (ks)*32 + tg*4;                \
    const uint32_t b0h_ = *(const uint32_t*)(kb_);                            \
    const uint32_t b1h_ = *(const uint32_t*)(kb_ + 16);                       \
    const uint32_t b0l_ = *(const uint32_t*)(kb_ + A_LOFF);                   \
    const uint32_t b1l_ = *(const uint32_t*)(kb_ + A_LOFF + 16);              \
    MMA16816(s##nt##0, s##nt##1, s##nt##2, s##nt##3,                          \
             qh##ks##0, qh##ks##1, qh##ks##2, qh##ks##3, b0h_, b1h_);         \
    MMA16816(s##nt##0, s##nt##1, s##nt##2, s##nt##3,                          \
             qh##ks##0, qh##ks##1, qh##ks##2, qh##ks##3, b0l_, b1l_);         \
    MMA16816(s##nt##0, s##nt##1, s##nt##2, s##nt##3,                          \
             ql##ks##0, ql##ks##1, ql##ks##2, ql##ks##3, b0h_, b1h_);         \
} while (0)

#define ASMMA_ALLNT(ks) do {                                                  \
    ASMMA(ks,0); ASMMA(ks,1); ASMMA(ks,2); ASMMA(ks,3);                       \
    ASMMA(ks,4); ASMMA(ks,5); ASMMA(ks,6); ASMMA(ks,7); } while (0)

#define AROWMAX(nt) do {                                                      \
    mxA = fmaxf(mxA, fmaxf(s##nt##0, s##nt##1));                              \
    mxB = fmaxf(mxB, fmaxf(s##nt##2, s##nt##3)); } while (0)

#define ASOFT(nt) do {                                                        \
    const float p0_ = fexp(s##nt##0 - mxA);                                   \
    const float p1_ = fexp(s##nt##1 - mxA);                                   \
    const float p2_ = fexp(s##nt##2 - mxB);                                   \
    const float p3_ = fexp(s##nt##3 - mxB);                                   \
    sumA += p0_ + p1_; sumB += p2_ + p3_;                                     \
    splitpack2(p0_, p1_, pha##nt, pla##nt);                                   \
    splitpack2(p2_, p3_, phb##nt, plb##nt);                                   \
    o##nt##0 *= corrA; o##nt##1 *= corrA;                                     \
    o##nt##2 *= corrB; o##nt##3 *= corrB; } while (0)

#define APVMMA(ks,ta,tb,nt) do {                                              \
    const char* vb_ = smc + A_VOFF + ((nt)*8+g)*AROWB + (ks)*32 + tg*4;       \
    const uint32_t b0h_ = *(const uint32_t*)(vb_);                            \
    const uint32_t b1h_ = *(const uint32_t*)(vb_ + 16);                       \
    const uint32_t b0l_ = *(const uint32_t*)(vb_ + A_LOFF);                   \
    const uint32_t b1l_ = *(const uint32_t*)(vb_ + A_LOFF + 16);              \
    MMA16816(o##nt##0, o##nt##1, o##nt##2, o##nt##3,                          \
             pha##ta, phb##ta, pha##tb, phb##tb, b0h_, b1h_);                 \
    MMA16816(o##nt##0, o##nt##1, o##nt##2, o##nt##3,                          \
             pha##ta, phb##ta, pha##tb, phb##tb, b0l_, b1l_);                 \
    MMA16816(o##nt##0, o##nt##1, o##nt##2, o##nt##3,                          \
             pla##ta, plb##ta, pla##tb, plb##tb, b0h_, b1h_);                 \
} while (0)

#define APVMMA_ALLNT(ks,ta,tb) do {                                           \
    APVMMA(ks,ta,tb,0); APVMMA(ks,ta,tb,1); APVMMA(ks,ta,tb,2);               \
    APVMMA(ks,ta,tb,3); APVMMA(ks,ta,tb,4); APVMMA(ks,ta,tb,5);               \
    APVMMA(ks,ta,tb,6); APVMMA(ks,ta,tb,7); } while (0)

#define AWRITE(nt) do {                                                       \
    *(float2*)(OgA + (nt)*8 + 2*tg) = make_float2(o##nt##0*invA, o##nt##1*invA); \
    *(float2*)(OgB + (nt)*8 + 2*tg) = make_float2(o##nt##2*invB, o##nt##3*invB); \
} while (0)

__global__ void __launch_bounds__(256, 1) attn_hmma_kernel()
{
    __shared__ __align__(16) char smc[ATT_SMEM];
    const int tid  = threadIdx.x;
    const int lane = tid & 31;
    const int warp = tid >> 5;
    const int g    = lane >> 2;
    const int tg   = lane & 3;
    const int combo = blockIdx.z;
    const int bh    = blockIdx.y;
    const int q0    = blockIdx.x * 128;
    const int qs    = combo >> 1;
    const int kvs   = ((combo + 1) >> 1) & 1;

    const float* __restrict__ Qg = g_q + ((size_t)(qs  * NB * NH) + bh) * NSEQ * DH;
    const float* __restrict__ Kg = g_k + ((size_t)(kvs * NB * NH) + bh) * NSEQ * DH;
    const float* __restrict__ Vg = g_v + ((size_t)(kvs * NB * NH) + bh) * DH * NSEQ;

    // Q fragments (scaled, split) held in registers for the whole block
    const float* Qrow0 = Qg + (size_t)(q0 + warp * 16 + g) * DH;
    const float* Qrow1 = Qrow0 + 8 * DH;
    LOADQ(0); LOADQ(1); LOADQ(2); LOADQ(3);

    ADECL_O(0); ADECL_O(1); ADECL_O(2); ADECL_O(3);
    ADECL_O(4); ADECL_O(5); ADECL_O(6); ADECL_O(7);
    float mA = -1e30f, mB = -1e30f, lA = 0.f, lB = 0.f;

    // staging maps
    const int srow = tid >> 2;              // key for K, d for V
    const int sseg = (tid & 3) * 16;        // 16-float segment
    const float* krB = Kg + (size_t)srow * DH + sseg;
    const float* vrB = Vg + (size_t)srow * NSEQ + sseg;
    char* kdh = smc + srow * AROWB + sseg * 2;
    char* vdh = smc + A_VOFF + srow * AROWB + sseg * 2;

    for (int kt = 0; kt < NSEQ / 64; kt++) {
        const int k0 = kt * 64;
        if (kt) __syncthreads();
        // stage K (key-major) and V (d-major) as bf16 hi/lo
        #pragma unroll
        for (int j = 0; j < 4; j++) {
            float4 f = *(const float4*)(krB + (size_t)k0 * DH + j * 4);
            uint32_t h0, l0, h1, l1;
            splitpack2(f.x, f.y, h0, l0);
            splitpack2(f.z, f.w, h1, l1);
            *(uint2*)(kdh + j * 8)          = make_uint2(h0, h1);
            *(uint2*)(kdh + A_LOFF + j * 8) = make_uint2(l0, l1);
            float4 v = *(const float4*)(vrB + k0 + j * 4);
            splitpack2(v.x, v.y, h0, l0);
            splitpack2(v.z, v.w, h1, l1);
            *(uint2*)(vdh + j * 8)          = make_uint2(h0, h1);
            *(uint2*)(vdh + A_LOFF + j * 8) = make_uint2(l0, l1);
        }
        __syncthreads();

        // S = Q K^T
        ADECL_S(0); ADECL_S(1); ADECL_S(2); ADECL_S(3);
        ADECL_S(4); ADECL_S(5); ADECL_S(6); ADECL_S(7);
        ASMMA_ALLNT(0); ASMMA_ALLNT(1); ASMMA_ALLNT(2); ASMMA_ALLNT(3);

        // online softmax
        float mxA = mA, mxB = mB;
        AROWMAX(0); AROWMAX(1); AROWMAX(2); AROWMAX(3);
        AROWMAX(4); AROWMAX(5); AROWMAX(6); AROWMAX(7);
        mxA = fmaxf(mxA, __shfl_xor_sync(0xffffffffu, mxA, 1));
        mxA = fmaxf(mxA, __shfl_xor_sync(0xffffffffu, mxA, 2));
        mxB = fmaxf(mxB, __shfl_xor_sync(0xffffffffu, mxB, 1));
        mxB = fmaxf(mxB, __shfl_xor_sync(0xffffffffu, mxB, 2));
        const float corrA = fexp(mA - mxA);
        const float corrB = fexp(mB - mxB);
        float sumA = 0.f, sumB = 0.f;
        ADECL_P(0); ADECL_P(1); ADECL_P(2); ADECL_P(3);
        ADECL_P(4); ADECL_P(5); ADECL_P(6); ADECL_P(7);
        ASOFT(0); ASOFT(1); ASOFT(2); ASOFT(3);
        ASOFT(4); ASOFT(5); ASOFT(6); ASOFT(7);
        sumA += __shfl_xor_sync(0xffffffffu, sumA, 1);
        sumA += __shfl_xor_sync(0xffffffffu, sumA, 2);
        sumB += __shfl_xor_sync(0xffffffffu, sumB, 1);
        sumB += __shfl_xor_sync(0xffffffffu, sumB, 2);
        lA = lA * corrA + sumA;
        lB = lB * corrB + sumB;
        mA = mxA; mB = mxB;

        // O += P V
        APVMMA_ALLNT(0,0,1); APVMMA_ALLNT(1,2,3);
        APVMMA_ALLNT(2,4,5); APVMMA_ALLNT(3,6,7);
    }

    const int b = bh / NH, h = bh - (bh / NH) * NH;
    const int row0 = q0 + warp * 16 + g;
    float* OgA = g_attn + ((size_t)(combo * NB + b) * NSEQ + row0) * DIM + h * DH;
    float* OgB = OgA + 8 * DIM;
    const float invA = 1.f / lA, invB = 1.f / lB;
    AWRITE(0); AWRITE(1); AWRITE(2); AWRITE(3);
    AWRITE(4); AWRITE(5); AWRITE(6); AWRITE(7);
}

// ============================ launch ========================================
extern "C" void kernel_launch(void* const* d_in, const int* in_sizes, int n_in,
                              void* d_out, int out_size)
{
    const float* x1    = (const float*)d_in[0];
    const float* x2    = (const float*)d_in[1];
    const float* Wqkv1 = (const float*)d_in[2];
    const float* Wqkv2 = (const float*)d_in[3];
    const float* Wp1   = (const float*)d_in[4];
    const float* bp1   = (const float*)d_in[5];
    const float* Wp2   = (const float*)d_in[6];
    const float* bp2   = (const float*)d_in[7];
    float* out = (float*)d_out;

    // QKV: C[2048 x 2304] per stream (V scattered transposed)
    hmma_gemm_kernel<<<dim3(NQKV / 64, MTOT / 128, 2), 256>>>(
        x1, x2, Wqkv1, Wqkv2, NQKV, 0, nullptr, nullptr, nullptr);

    attn_hmma_kernel<<<dim3(8, 24, 4), 256>>>();

    // proj: C[2048 x 768] per stream, A = attn combo sums
    hmma_gemm_kernel<<<dim3(DIM / 64, MTOT / 128, 2), 256>>>(
        nullptr, nullptr, Wp1, Wp2, DIM, 1, bp1, bp2, out);
}

// round 9
// speedup vs baseline: 1.9065x; 1.0689x over previous
#include <cuda_runtime.h>
#include <cuda_bf16.h>
#include <cstdint>

// ----------------------------------------------------------------------------
// CrossAttention, Round 9:
//   - Both HMMA kernels: ldmatrix.x4 fragment loads (4x fewer smem instrs)
//     and double-buffered smem with ONE __syncthreads per chunk (was two).
//   - Everything else (bf16x3 split math, layouts, epilogues) unchanged
//     from the passing Round-8 kernel. Statics still 62.9MB (arena-safe).
// ----------------------------------------------------------------------------

#define NB    2
#define NSEQ  1024
#define DIM   768
#define NH    12
#define DH    64
#define QSCALE 0.125f

#define MTOT  (NB*NSEQ)        // 2048
#define NQKV  (3*DIM)          // 2304
#define KDIM  DIM              // 768
#define KC    32
#define NCH   (KDIM/KC)        // 24

#define QKV_ELEMS (2*NB*NH*NSEQ*DH)
__device__ float g_q[QKV_ELEMS];           // [s][b][h][n][d]
__device__ float g_k[QKV_ELEMS];           // [s][b][h][n][d]
__device__ float g_v[QKV_ELEMS];           // [s][b][h][d][n]  (TRANSPOSED)
__device__ float g_attn[4*NB*NSEQ*DIM];

// ============================ helpers =======================================
__device__ __forceinline__ uint32_t s2u(const void* p) {
    uint32_t a;
    asm("{ .reg .u64 t; cvta.to.shared.u64 t, %1; cvt.u32.u64 %0, t; }"
        : "=r"(a) : "l"(p));
    return a;
}

#define MMA16816(d0,d1,d2,d3,a0,a1,a2,a3,b0,b1)                               \
    asm volatile(                                                             \
        "mma.sync.aligned.m16n8k16.row.col.f32.bf16.bf16.f32 "                \
        "{%0,%1,%2,%3}, {%4,%5,%6,%7}, {%8,%9}, {%0,%1,%2,%3};"               \
        : "+f"(d0), "+f"(d1), "+f"(d2), "+f"(d3)                              \
        : "r"(a0), "r"(a1), "r"(a2), "r"(a3), "r"(b0), "r"(b1))

#define LDSM4(r0,r1,r2,r3,addr)                                               \
    asm volatile("ldmatrix.sync.aligned.m8n8.x4.shared.b16 {%0,%1,%2,%3}, [%4];" \
        : "=r"(r0), "=r"(r1), "=r"(r2), "=r"(r3) : "r"(addr))

__device__ __forceinline__ void split2(float v, __nv_bfloat16& h, __nv_bfloat16& l) {
    h = __float2bfloat16_rn(v);
    l = __float2bfloat16_rn(v - __bfloat162float(h));
}

__device__ __forceinline__ void splitpack2(float x, float y,
                                           uint32_t& hp, uint32_t& lp) {
    __nv_bfloat16 hx = __float2bfloat16_rn(x);
    __nv_bfloat16 hy = __float2bfloat16_rn(y);
    __nv_bfloat16 lx = __float2bfloat16_rn(x - __bfloat162float(hx));
    __nv_bfloat16 ly = __float2bfloat16_rn(y - __bfloat162float(hy));
    hp = (uint32_t)__bfloat16_as_ushort(hx) | ((uint32_t)__bfloat16_as_ushort(hy) << 16);
    lp = (uint32_t)__bfloat16_as_ushort(lx) | ((uint32_t)__bfloat16_as_ushort(ly) << 16);
}

__device__ __forceinline__ float fexp(float x) {
    x = fmaxf(x, -87.0f);
    float y = x * 1.4426950408889634f;
    float t = y + 12582912.0f;
    int   n = __float_as_int(t) - 0x4B400000;
    float f = y - (t - 12582912.0f);
    float p = 1.33335581e-3f;
    p = fmaf(p, f, 9.61812911e-3f);
    p = fmaf(p, f, 5.55041086e-2f);
    p = fmaf(p, f, 2.40226512e-1f);
    p = fmaf(p, f, 6.93147182e-1f);
    p = fmaf(p, f, 1.0f);
    float s = __int_as_float((n + 127) << 23);
    return p * s;
}

// ============================ HMMA GEMM =====================================
#define ROWB   80
#define OFF_AH 0
#define OFF_AL (128*ROWB)          // 10240
#define OFF_BH (2*128*ROWB)        // 20480
#define OFF_BL (OFF_BH + 64*ROWB)  // 25600
#define STAGEB (OFF_BL + 64*ROWB)  // 30720
#define GEMM_SMEM (2*STAGEB)       // 61440

#define DECL_ACC(mt,nt) \
    float c##mt##nt##0 = 0.f, c##mt##nt##1 = 0.f, c##mt##nt##2 = 0.f, c##mt##nt##3 = 0.f

#define MMA3(mt,nt) \
    MMA16816(c##mt##nt##0, c##mt##nt##1, c##mt##nt##2, c##mt##nt##3,          \
             ah0, ah1, ah2, ah3, bh##nt##0, bh##nt##1);                       \
    MMA16816(c##mt##nt##0, c##mt##nt##1, c##mt##nt##2, c##mt##nt##3,          \
             ah0, ah1, ah2, ah3, bl##nt##0, bl##nt##1);                       \
    MMA16816(c##mt##nt##0, c##mt##nt##1, c##mt##nt##2, c##mt##nt##3,          \
             al0, al1, al2, al3, bh##nt##0, bh##nt##1)

#define EPILOG(mt,nt) do {                                                    \
    const int row0 = m0 + wm * 32 + (mt) * 16 + g;                            \
    const int colg = n0 + wn * 32 + (nt) * 8 + 2 * tg;                        \
    const float e0 = c##mt##nt##0, e1 = c##mt##nt##1;                         \
    const float e2 = c##mt##nt##2, e3 = c##mt##nt##3;                         \
    if (mode == 0) {                                                          \
        const int t3  = colg / DIM;                                           \
        const int rem = colg - t3 * DIM;                                      \
        const int h   = rem >> 6;                                             \
        const int d0  = rem & 63;                                             \
        const int m1_ = row0,     b1_ = m1_ >> 10, nq1 = m1_ & (NSEQ - 1);    \
        const int m2_ = row0 + 8, b2_ = m2_ >> 10, nq2 = m2_ & (NSEQ - 1);    \
        if (t3 == 2) {                                                        \
            const size_t vb1 = (((size_t)(s * NB + b1_) * NH + h) * DH + d0) * NSEQ + nq1; \
            const size_t vb2 = (((size_t)(s * NB + b2_) * NH + h) * DH + d0) * NSEQ + nq2; \
            g_v[vb1] = e0; g_v[vb1 + NSEQ] = e1;                              \
            g_v[vb2] = e2; g_v[vb2 + NSEQ] = e3;                              \
        } else {                                                              \
            float* dst = (t3 == 0) ? g_q : g_k;                               \
            *(float2*)(dst + ((((size_t)(s * NB + b1_) * NH + h) * NSEQ + nq1) * DH + d0)) \
                = make_float2(e0, e1);                                        \
            *(float2*)(dst + ((((size_t)(s * NB + b2_) * NH + h) * NSEQ + nq2) * DH + d0)) \
                = make_float2(e2, e3);                                        \
        }                                                                     \
    } else {                                                                  \
        const float* bias = s ? bias2 : bias1;                                \
        const float bx = bias[colg], by = bias[colg + 1];                     \
        *(float2*)(out + ((size_t)s * MTOT + row0) * DIM + colg)              \
            = make_float2(e0 + bx, e1 + by);                                  \
        *(float2*)(out + ((size_t)s * MTOT + row0 + 8) * DIM + colg)          \
            = make_float2(e2 + bx, e3 + by);                                  \
    }                                                                         \
} while (0)

#define STAGE_LOAD_A(cc) do {                                                 \
    const float* _p = pA0 + (cc) * KC;                                        \
    _Pragma("unroll")                                                         \
    for (int i4 = 0; i4 < 4; i4++) {                                          \
        float4 v = *(const float4*)(_p + i4 * 4);                             \
        if (mode == 1) {                                                      \
            float4 w = *(const float4*)(pA1 + (cc) * KC + i4 * 4);            \
            v.x += w.x; v.y += w.y; v.z += w.z; v.w += w.w;                   \
        }                                                                     \
        ar[i4 * 4 + 0] = v.x; ar[i4 * 4 + 1] = v.y;                           \
        ar[i4 * 4 + 2] = v.z; ar[i4 * 4 + 3] = v.w;                           \
    }                                                                         \
} while (0)

#define STAGE_LOAD_B(cc) do {                                                 \
    _Pragma("unroll")                                                         \
    for (int p = 0; p < 2; p++) {                                             \
        float4 v = *(const float4*)(pB + ((size_t)(cc) * KC + p * 16) * Ntot);\
        br[p * 4 + 0] = v.x; br[p * 4 + 1] = v.y;                             \
        br[p * 4 + 2] = v.z; br[p * 4 + 3] = v.w;                             \
    }                                                                         \
} while (0)

__global__ void __launch_bounds__(256, 2) hmma_gemm_kernel(
    const float* __restrict__ A1g, const float* __restrict__ A2g,
    const float* __restrict__ B1g, const float* __restrict__ B2g,
    int Ntot, int mode,
    const float* __restrict__ bias1, const float* __restrict__ bias2,
    float* __restrict__ out)
{
    extern __shared__ __align__(16) char smc[];
    const uint32_t sb = s2u(smc);
    const int tid  = threadIdx.x;
    const int lane = tid & 31;
    const int warp = tid >> 5;
    const int wm   = warp >> 1;
    const int wn   = warp & 1;
    const int g    = lane >> 2;
    const int tg   = lane & 3;
    const int s    = blockIdx.z;
    const int m0   = blockIdx.y * 128;
    const int n0   = blockIdx.x * 64;

    const int arow = tid >> 1;
    const int akb  = (tid & 1) * 16;
    const float* pA0;
    const float* pA1 = nullptr;
    if (mode == 0) {
        const float* Ag = s ? A2g : A1g;
        pA0 = Ag + (size_t)(m0 + arow) * KDIM + akb;
    } else {
        const size_t per = (size_t)MTOT * KDIM;
        pA0 = g_attn + (size_t)(2 * s) * per + (size_t)(m0 + arow) * KDIM + akb;
        pA1 = pA0 + per;
    }

    const float* Bg = s ? B2g : B1g;
    const int kkB = tid >> 4;
    const int nnB = (tid & 15) * 4;
    const float* pB = Bg + (size_t)kkB * Ntot + n0 + nnB;

    // per-lane ldmatrix base addresses (buffer offset + kk*32 added at use)
    const uint32_t aA0 = sb + OFF_AH + (uint32_t)((wm * 32 + (lane & 15)) * ROWB + (lane >> 4) * 16);
    const uint32_t aA1 = aA0 + 16 * ROWB;
    const int bro = (lane & 7) + ((lane >> 4) << 3);
    const uint32_t aB0 = sb + OFF_BH + (uint32_t)((wn * 32 + bro) * ROWB + ((lane >> 3) & 1) * 16);
    const uint32_t aB1 = aB0 + 16 * ROWB;

    DECL_ACC(0,0); DECL_ACC(0,1); DECL_ACC(0,2); DECL_ACC(0,3);
    DECL_ACC(1,0); DECL_ACC(1,1); DECL_ACC(1,2); DECL_ACC(1,3);

    float ar[16];
    float br[8];
    STAGE_LOAD_A(0);
    STAGE_LOAD_B(0);

    for (int c = 0; c < NCH; c++) {
        const uint32_t boff = (uint32_t)((c & 1) * STAGEB);
        // ---- convert & store staged chunk into buf[c&1] ----
        {
            char* bufp = smc + (c & 1) * STAGEB;
            char* adst = bufp + arow * ROWB + akb * 2;
            #pragma unroll
            for (int i = 0; i < 8; i++) {
                uint32_t hp, lp;
                splitpack2(ar[2 * i], ar[2 * i + 1], hp, lp);
                *(uint32_t*)(adst + OFF_AH + i * 4) = hp;
                *(uint32_t*)(adst + OFF_AL + i * 4) = lp;
            }
            #pragma unroll
            for (int p = 0; p < 2; p++) {
                const int kchunk = kkB + p * 16;
                #pragma unroll
                for (int j = 0; j < 4; j++) {
                    __nv_bfloat16 h, l;
                    split2(br[p * 4 + j], h, l);
                    const int n = nnB + j;
                    *(__nv_bfloat16*)(bufp + OFF_BH + n * ROWB + kchunk * 2) = h;
                    *(__nv_bfloat16*)(bufp + OFF_BL + n * ROWB + kchunk * 2) = l;
                }
            }
        }
        __syncthreads();   // single sync per chunk (double-buffered)

        // ---- prefetch next chunk ----
        if (c + 1 < NCH) {
            STAGE_LOAD_A(c + 1);
            STAGE_LOAD_B(c + 1);
        }

        // ---- ldmatrix + MMAs ----
        #pragma unroll
        for (int kk = 0; kk < 2; kk++) {
            const uint32_t ko = boff + kk * 32;
            uint32_t bh00, bh01, bh10, bh11, bl00, bl01, bl10, bl11;
            uint32_t bh20, bh21, bh30, bh31, bl20, bl21, bl30, bl31;
            LDSM4(bh00, bh01, bh10, bh11, aB0 + ko);
            LDSM4(bl00, bl01, bl10, bl11, aB0 + ko + 5120);
            LDSM4(bh20, bh21, bh30, bh31, aB1 + ko);
            LDSM4(bl20, bl21, bl30, bl31, aB1 + ko + 5120);
            {
                uint32_t ah0, ah1, ah2, ah3, al0, al1, al2, al3;
                LDSM4(ah0, ah1, ah2, ah3, aA0 + ko);
                LDSM4(al0, al1, al2, al3, aA0 + ko + OFF_AL);
                MMA3(0,0); MMA3(0,1); MMA3(0,2); MMA3(0,3);
            }
            {
                uint32_t ah0, ah1, ah2, ah3, al0, al1, al2, al3;
                LDSM4(ah0, ah1, ah2, ah3, aA1 + ko);
                LDSM4(al0, al1, al2, al3, aA1 + ko + OFF_AL);
                MMA3(1,0); MMA3(1,1); MMA3(1,2); MMA3(1,3);
            }
        }
    }

    EPILOG(0,0); EPILOG(0,1); EPILOG(0,2); EPILOG(0,3);
    EPILOG(1,0); EPILOG(1,1); EPILOG(1,2); EPILOG(1,3);
}

// ============================ HMMA attention ================================
#define AROWB  144
#define A_VOFF (2*64*AROWB)         // 18432
#define A_LOFF (64*AROWB)           // 9216
#define ATT_SMEM (4*64*AROWB)       // 36864
#define ATT_SMEM2 (2*ATT_SMEM)      // 73728

#define LOADQ(ks)                                                             \
    uint32_t qh##ks##0, qh##ks##1, qh##ks##2, qh##ks##3;                      \
    uint32_t ql##ks##0, ql##ks##1, ql##ks##2, ql##ks##3;                      \
    do {                                                                      \
        const float2 fa = *(const float2*)(Qrow0 + (ks)*16 + 2*tg);           \
        const float2 fb = *(const float2*)(Qrow1 + (ks)*16 + 2*tg);           \
        const float2 fc = *(const float2*)(Qrow0 + (ks)*16 + 8 + 2*tg);       \
        const float2 fd = *(const float2*)(Qrow1 + (ks)*16 + 8 + 2*tg);       \
        splitpack2(fa.x*QSCALE, fa.y*QSCALE, qh##ks##0, ql##ks##0);           \
        splitpack2(fb.x*QSCALE, fb.y*QSCALE, qh##ks##1, ql##ks##1);           \
        splitpack2(fc.x*QSCALE, fc.y*QSCALE, qh##ks##2, ql##ks##2);           \
        splitpack2(fd.x*QSCALE, fd.y*QSCALE, qh##ks##3, ql##ks##3);           \
    } while (0)

#define ADECL_S(nt) float s##nt##0=0.f, s##nt##1=0.f, s##nt##2=0.f, s##nt##3=0.f
#define ADECL_O(nt) float o##nt##0=0.f, o##nt##1=0.f, o##nt##2=0.f, o##nt##3=0.f
#define ADECL_P(nt) uint32_t pha##nt=0u, phb##nt=0u, pla##nt=0u, plb##nt=0u

// S-phase pair: ldmatrix K frags for n-tiles (na, nb) = (2p, 2p+1)
#define ASMMA_P(ks,p,na,nb) do {                                              \
    uint32_t kh0,kh1,kh2,kh3, kl0,kl1,kl2,kl3;                                \
    LDSM4(kh0,kh1,kh2,kh3, aK##p + abuf + (ks)*32);                           \
    LDSM4(kl0,kl1,kl2,kl3, aK##p + abuf + A_LOFF + (ks)*32);                  \
    MMA16816(s##na##0,s##na##1,s##na##2,s##na##3,                             \
             qh##ks##0,qh##ks##1,qh##ks##2,qh##ks##3, kh0,kh1);               \
    MMA16816(s##na##0,s##na##1,s##na##2,s##na##3,                             \
             qh##ks##0,qh##ks##1,qh##ks##2,qh##ks##3, kl0,kl1);               \
    MMA16816(s##na##0,s##na##1,s##na##2,s##na##3,                             \
             ql##ks##0,ql##ks##1,ql##ks##2,ql##ks##3, kh0,kh1);               \
    MMA16816(s##nb##0,s##nb##1,s##nb##2,s##nb##3,                             \
             qh##ks##0,qh##ks##1,qh##ks##2,qh##ks##3, kh2,kh3);               \
    MMA16816(s##nb##0,s##nb##1,s##nb##2,s##nb##3,                             \
             qh##ks##0,qh##ks##1,qh##ks##2,qh##ks##3, kl2,kl3);               \
    MMA16816(s##nb##0,s##nb##1,s##nb##2,s##nb##3,                             \
             ql##ks##0,ql##ks##1,ql##ks##2,ql##ks##3, kh2,kh3);               \
} while (0)

#define ASMMA_ALLNT(ks) do {                                                  \
    ASMMA_P(ks,0,0,1); ASMMA_P(ks,1,2,3);                                     \
    ASMMA_P(ks,2,4,5); ASMMA_P(ks,3,6,7); } while (0)

#define AROWMAX(nt) do {                                                      \
    mxA = fmaxf(mxA, fmaxf(s##nt##0, s##nt##1));                              \
    mxB = fmaxf(mxB, fmaxf(s##nt##2, s##nt##3)); } while (0)

#define ASOFT(nt) do {                                                        \
    const float p0_ = fexp(s##nt##0 - mxA);                                   \
    const float p1_ = fexp(s##nt##1 - mxA);                                   \
    const float p2_ = fexp(s##nt##2 - mxB);                                   \
    const float p3_ = fexp(s##nt##3 - mxB);                                   \
    sumA += p0_ + p1_; sumB += p2_ + p3_;                                     \
    splitpack2(p0_, p1_, pha##nt, pla##nt);                                   \
    splitpack2(p2_, p3_, phb##nt, plb##nt);                                   \
    o##nt##0 *= corrA; o##nt##1 *= corrA;                                     \
    o##nt##2 *= corrB; o##nt##3 *= corrB; } while (0)

// PV-phase pair: ldmatrix V frags for d-tiles (na, nb) = (2p, 2p+1)
#define APV_P(ks,ta,tb,p,na,nb) do {                                          \
    uint32_t vh0,vh1,vh2,vh3, vl0,vl1,vl2,vl3;                                \
    LDSM4(vh0,vh1,vh2,vh3, aV##p + abuf + (ks)*32);                           \
    LDSM4(vl0,vl1,vl2,vl3, aV##p + abuf + A_LOFF + (ks)*32);                  \
    MMA16816(o##na##0,o##na##1,o##na##2,o##na##3,                             \
             pha##ta, phb##ta, pha##tb, phb##tb, vh0,vh1);                    \
    MMA16816(o##na##0,o##na##1,o##na##2,o##na##3,                             \
             pha##ta, phb##ta, pha##tb, phb##tb, vl0,vl1);                    \
    MMA16816(o##na##0,o##na##1,o##na##2,o##na##3,                             \
             pla##ta, plb##ta, pla##tb, plb##tb, vh0,vh1);                    \
    MMA16816(o##nb##0,o##nb##1,o##nb##2,o##nb##3,                             \
             pha##ta, phb##ta, pha##tb, phb##tb, vh2,vh3);                    \
    MMA16816(o##nb##0,o##nb##1,o##nb##2,o##nb##3,                             \
             pha##ta, phb##ta, pha##tb, phb##tb, vl2,vl3);                    \
    MMA16816(o##nb##0,o##nb##1,o##nb##2,o##nb##3,                             \
             pla##ta, plb##ta, pla##tb, plb##tb, vh2,vh3);                    \
} while (0)

#define APVMMA_ALLNT(ks,ta,tb) do {                                           \
    APV_P(ks,ta,tb,0,0,1); APV_P(ks,ta,tb,1,2,3);                             \
    APV_P(ks,ta,tb,2,4,5); APV_P(ks,ta,tb,3,6,7); } while (0)

#define AWRITE(nt) do {                                                       \
    *(float2*)(OgA + (nt)*8 + 2*tg) = make_float2(o##nt##0*invA, o##nt##1*invA); \
    *(float2*)(OgB + (nt)*8 + 2*tg) = make_float2(o##nt##2*invB, o##nt##3*invB); \
} while (0)

__global__ void __launch_bounds__(256, 1) attn_hmma_kernel()
{
    extern __shared__ __align__(16) char smc[];
    const uint32_t sb = s2u(smc);
    const int tid  = threadIdx.x;
    const int lane = tid & 31;
    const int warp = tid >> 5;
    const int g    = lane >> 2;
    const int tg   = lane & 3;
    const int combo = blockIdx.z;
    const int bh    = blockIdx.y;
    const int q0    = blockIdx.x * 128;
    const int qs    = combo >> 1;
    const int kvs   = ((combo + 1) >> 1) & 1;

    const float* __restrict__ Qg = g_q + ((size_t)(qs  * NB * NH) + bh) * NSEQ * DH;
    const float* __restrict__ Kg = g_k + ((size_t)(kvs * NB * NH) + bh) * NSEQ * DH;
    const float* __restrict__ Vg = g_v + ((size_t)(kvs * NB * NH) + bh) * DH * NSEQ;

    const float* Qrow0 = Qg + (size_t)(q0 + warp * 16 + g) * DH;
    const float* Qrow1 = Qrow0 + 8 * DH;
    LOADQ(0); LOADQ(1); LOADQ(2); LOADQ(3);

    ADECL_O(0); ADECL_O(1); ADECL_O(2); ADECL_O(3);
    ADECL_O(4); ADECL_O(5); ADECL_O(6); ADECL_O(7);
    float mA = -1e30f, mB = -1e30f, lA = 0.f, lB = 0.f;

    // staging maps
    const int srow = tid >> 2;
    const int sseg = (tid & 3) * 16;
    const float* krB = Kg + (size_t)srow * DH + sseg;
    const float* vrB = Vg + (size_t)srow * NSEQ + sseg;
    char* kdh = smc + srow * AROWB + sseg * 2;
    char* vdh = smc + A_VOFF + srow * AROWB + sseg * 2;

    // per-lane ldmatrix base addresses (B-frag map; K region and V region)
    const int bro = (lane & 7) + ((lane >> 4) << 3);
    const uint32_t kb16 = ((lane >> 3) & 1) * 16;
    const uint32_t aK0 = sb + (uint32_t)((0  + bro) * AROWB) + kb16;
    const uint32_t aK1 = aK0 + 16 * AROWB;
    const uint32_t aK2 = aK0 + 32 * AROWB;
    const uint32_t aK3 = aK0 + 48 * AROWB;
    const uint32_t aV0 = aK0 + A_VOFF;
    const uint32_t aV1 = aK1 + A_VOFF;
    const uint32_t aV2 = aK2 + A_VOFF;
    const uint32_t aV3 = aK3 + A_VOFF;

    for (int kt = 0; kt < NSEQ / 64; kt++) {
        const int k0 = kt * 64;
        const int ab = (kt & 1) * ATT_SMEM;
        // stage K (key-major) and V (d-major) bf16 hi/lo into buf[kt&1]
        #pragma unroll
        for (int j = 0; j < 4; j++) {
            float4 f = *(const float4*)(krB + (size_t)k0 * DH + j * 4);
            uint32_t h0, l0, h1, l1;
            splitpack2(f.x, f.y, h0, l0);
            splitpack2(f.z, f.w, h1, l1);
            *(uint2*)(kdh + ab + j * 8)          = make_uint2(h0, h1);
            *(uint2*)(kdh + ab + A_LOFF + j * 8) = make_uint2(l0, l1);
            float4 v = *(const float4*)(vrB + k0 + j * 4);
            splitpack2(v.x, v.y, h0, l0);
            splitpack2(v.z, v.w, h1, l1);
            *(uint2*)(vdh + ab + j * 8)          = make_uint2(h0, h1);
            *(uint2*)(vdh + ab + A_LOFF + j * 8) = make_uint2(l0, l1);
        }
        __syncthreads();   // single sync per tile (double-buffered)
        const uint32_t abuf = (uint32_t)ab;

        // S = Q K^T
        ADECL_S(0); ADECL_S(1); ADECL_S(2); ADECL_S(3);
        ADECL_S(4); ADECL_S(5); ADECL_S(6); ADECL_S(7);
        ASMMA_ALLNT(0); ASMMA_ALLNT(1); ASMMA_ALLNT(2); ASMMA_ALLNT(3);

        // online softmax
        float mxA = mA, mxB = mB;
        AROWMAX(0); AROWMAX(1); AROWMAX(2); AROWMAX(3);
        AROWMAX(4); AROWMAX(5); AROWMAX(6); AROWMAX(7);
        mxA = fmaxf(mxA, __shfl_xor_sync(0xffffffffu, mxA, 1));
        mxA = fmaxf(mxA, __shfl_xor_sync(0xffffffffu, mxA, 2));
        mxB = fmaxf(mxB, __shfl_xor_sync(0xffffffffu, mxB, 1));
        mxB = fmaxf(mxB, __shfl_xor_sync(0xffffffffu, mxB, 2));
        const float corrA = fexp(mA - mxA);
        const float corrB = fexp(mB - mxB);
        float sumA = 0.f, sumB = 0.f;
        ADECL_P(0); ADECL_P(1); ADECL_P(2); ADECL_P(3);
        ADECL_P(4); ADECL_P(5); ADECL_P(6); ADECL_P(7);
        ASOFT(0); ASOFT(1); ASOFT(2); ASOFT(3);
        ASOFT(4); ASOFT(5); ASOFT(6); ASOFT(7);
        sumA += __shfl_xor_sync(0xffffffffu, sumA, 1);
        sumA += __shfl_xor_sync(0xffffffffu, sumA, 2);
        sumB += __shfl_xor_sync(0xffffffffu, sumB, 1);
        sumB += __shfl_xor_sync(0xffffffffu, sumB, 2);
        lA = lA * corrA + sumA;
        lB = lB * corrB + sumB;
        mA = mxA; mB = mxB;

        // O += P V
        APVMMA_ALLNT(0,0,1); APVMMA_ALLNT(1,2,3);
        APVMMA_ALLNT(2,4,5); APVMMA_ALLNT(3,6,7);
    }

    const int b = bh / NH, h = bh - (bh / NH) * NH;
    const int row0 = q0 + warp * 16 + g;
    float* OgA = g_attn + ((size_t)(combo * NB + b) * NSEQ + row0) * DIM + h * DH;
    float* OgB = OgA + 8 * DIM;
    const float invA = 1.f / lA, invB = 1.f / lB;
    AWRITE(0); AWRITE(1); AWRITE(2); AWRITE(3);
    AWRITE(4); AWRITE(5); AWRITE(6); AWRITE(7);
}

// ============================ launch ========================================
extern "C" void kernel_launch(void* const* d_in, const int* in_sizes, int n_in,
                              void* d_out, int out_size)
{
    const float* x1    = (const float*)d_in[0];
    const float* x2    = (const float*)d_in[1];
    const float* Wqkv1 = (const float*)d_in[2];
    const float* Wqkv2 = (const float*)d_in[3];
    const float* Wp1   = (const float*)d_in[4];
    const float* bp1   = (const float*)d_in[5];
    const float* Wp2   = (const float*)d_in[6];
    const float* bp2   = (const float*)d_in[7];
    float* out = (float*)d_out;

    cudaFuncSetAttribute(hmma_gemm_kernel,
                         cudaFuncAttributeMaxDynamicSharedMemorySize, GEMM_SMEM);
    cudaFuncSetAttribute(attn_hmma_kernel,
                         cudaFuncAttributeMaxDynamicSharedMemorySize, ATT_SMEM2);

    hmma_gemm_kernel<<<dim3(NQKV / 64, MTOT / 128, 2), 256, GEMM_SMEM>>>(
        x1, x2, Wqkv1, Wqkv2, NQKV, 0, nullptr, nullptr, nullptr);

    attn_hmma_kernel<<<dim3(8, 24, 4), 256, ATT_SMEM2>>>();

    hmma_gemm_kernel<<<dim3(DIM / 64, MTOT / 128, 2), 256, GEMM_SMEM>>>(
        nullptr, nullptr, Wp1, Wp2, DIM, 1, bp1, bp2, out);
}

// round 10
// speedup vs baseline: 2.0062x; 1.0523x over previous
#include <cuda_runtime.h>
#include <cuda_bf16.h>
#include <cstdint>

// ----------------------------------------------------------------------------
// CrossAttention, Round 10:
//   - QKV epilogue now emits PRE-SPLIT bf16 hi/lo operands for attention:
//       g_qh/g_ql [n][d] (QSCALE baked in), g_kh/g_kl [n][d], g_vh/g_vl [d][n]
//   - attention staging is a pure copy (no per-tile fp32->bf16 conversion,
//     which was redone 16x per KV tile before), Q frags load pre-split.
//   - GEMM mainloop / attention MMA+softmax unchanged from Round 9.
//   Statics = 62,914,560 B, exactly the proven arena-safe footprint.
// ----------------------------------------------------------------------------

#define NB    2
#define NSEQ  1024
#define DIM   768
#define NH    12
#define DH    64
#define QSCALE 0.125f

#define MTOT  (NB*NSEQ)        // 2048
#define NQKV  (3*DIM)          // 2304
#define KDIM  DIM              // 768
#define KC    32
#define NCH   (KDIM/KC)        // 24

#define QKV_ELEMS (2*NB*NH*NSEQ*DH)     // 3,145,728
__device__ __align__(16) __nv_bfloat16 g_qh[QKV_ELEMS];  // [s][b][h][n][d], scaled
__device__ __align__(16) __nv_bfloat16 g_ql[QKV_ELEMS];
__device__ __align__(16) __nv_bfloat16 g_kh[QKV_ELEMS];  // [s][b][h][n][d]
__device__ __align__(16) __nv_bfloat16 g_kl[QKV_ELEMS];
__device__ __align__(16) __nv_bfloat16 g_vh[QKV_ELEMS];  // [s][b][h][d][n]
__device__ __align__(16) __nv_bfloat16 g_vl[QKV_ELEMS];
__device__ float g_attn[4*NB*NSEQ*DIM];
// total: 6*6,291,456 + 25,165,824 = 62,914,560 B

// ============================ helpers =======================================
__device__ __forceinline__ uint32_t s2u(const void* p) {
    uint32_t a;
    asm("{ .reg .u64 t; cvta.to.shared.u64 t, %1; cvt.u32.u64 %0, t; }"
        : "=r"(a) : "l"(p));
    return a;
}

#define MMA16816(d0,d1,d2,d3,a0,a1,a2,a3,b0,b1)                               \
    asm volatile(                                                             \
        "mma.sync.aligned.m16n8k16.row.col.f32.bf16.bf16.f32 "                \
        "{%0,%1,%2,%3}, {%4,%5,%6,%7}, {%8,%9}, {%0,%1,%2,%3};"               \
        : "+f"(d0), "+f"(d1), "+f"(d2), "+f"(d3)                              \
        : "r"(a0), "r"(a1), "r"(a2), "r"(a3), "r"(b0), "r"(b1))

#define LDSM4(r0,r1,r2,r3,addr)                                               \
    asm volatile("ldmatrix.sync.aligned.m8n8.x4.shared.b16 {%0,%1,%2,%3}, [%4];" \
        : "=r"(r0), "=r"(r1), "=r"(r2), "=r"(r3) : "r"(addr))

__device__ __forceinline__ void split2(float v, __nv_bfloat16& h, __nv_bfloat16& l) {
    h = __float2bfloat16_rn(v);
    l = __float2bfloat16_rn(v - __bfloat162float(h));
}

__device__ __forceinline__ void splitpack2(float x, float y,
                                           uint32_t& hp, uint32_t& lp) {
    __nv_bfloat16 hx = __float2bfloat16_rn(x);
    __nv_bfloat16 hy = __float2bfloat16_rn(y);
    __nv_bfloat16 lx = __float2bfloat16_rn(x - __bfloat162float(hx));
    __nv_bfloat16 ly = __float2bfloat16_rn(y - __bfloat162float(hy));
    hp = (uint32_t)__bfloat16_as_ushort(hx) | ((uint32_t)__bfloat16_as_ushort(hy) << 16);
    lp = (uint32_t)__bfloat16_as_ushort(lx) | ((uint32_t)__bfloat16_as_ushort(ly) << 16);
}

__device__ __forceinline__ float fexp(float x) {
    x = fmaxf(x, -87.0f);
    float y = x * 1.4426950408889634f;
    float t = y + 12582912.0f;
    int   n = __float_as_int(t) - 0x4B400000;
    float f = y - (t - 12582912.0f);
    float p = 1.33335581e-3f;
    p = fmaf(p, f, 9.61812911e-3f);
    p = fmaf(p, f, 5.55041086e-2f);
    p = fmaf(p, f, 2.40226512e-1f);
    p = fmaf(p, f, 6.93147182e-1f);
    p = fmaf(p, f, 1.0f);
    float s = __int_as_float((n + 127) << 23);
    return p * s;
}

// ============================ HMMA GEMM =====================================
#define ROWB   80
#define OFF_AH 0
#define OFF_AL (128*ROWB)          // 10240
#define OFF_BH (2*128*ROWB)        // 20480
#define OFF_BL (OFF_BH + 64*ROWB)  // 25600
#define STAGEB (OFF_BL + 64*ROWB)  // 30720
#define GEMM_SMEM (2*STAGEB)       // 61440

#define DECL_ACC(mt,nt) \
    float c##mt##nt##0 = 0.f, c##mt##nt##1 = 0.f, c##mt##nt##2 = 0.f, c##mt##nt##3 = 0.f

#define MMA3(mt,nt) \
    MMA16816(c##mt##nt##0, c##mt##nt##1, c##mt##nt##2, c##mt##nt##3,          \
             ah0, ah1, ah2, ah3, bh##nt##0, bh##nt##1);                       \
    MMA16816(c##mt##nt##0, c##mt##nt##1, c##mt##nt##2, c##mt##nt##3,          \
             ah0, ah1, ah2, ah3, bl##nt##0, bl##nt##1);                       \
    MMA16816(c##mt##nt##0, c##mt##nt##1, c##mt##nt##2, c##mt##nt##3,          \
             al0, al1, al2, al3, bh##nt##0, bh##nt##1)

#define EPILOG(mt,nt) do {                                                    \
    const int row0 = m0 + wm * 32 + (mt) * 16 + g;                            \
    const int colg = n0 + wn * 32 + (nt) * 8 + 2 * tg;                        \
    const float e0 = c##mt##nt##0, e1 = c##mt##nt##1;                         \
    const float e2 = c##mt##nt##2, e3 = c##mt##nt##3;                         \
    if (mode == 0) {                                                          \
        const int t3  = colg / DIM;                                           \
        const int rem = colg - t3 * DIM;                                      \
        const int h   = rem >> 6;                                             \
        const int d0  = rem & 63;                                             \
        const int m1_ = row0,     b1_ = m1_ >> 10, nq1 = m1_ & (NSEQ - 1);    \
        const int m2_ = row0 + 8, b2_ = m2_ >> 10, nq2 = m2_ & (NSEQ - 1);    \
        if (t3 == 2) {                                                        \
            const size_t vb1 = (((size_t)(s * NB + b1_) * NH + h) * DH + d0) * NSEQ + nq1; \
            const size_t vb2 = (((size_t)(s * NB + b2_) * NH + h) * DH + d0) * NSEQ + nq2; \
            __nv_bfloat16 h_, l_;                                             \
            split2(e0, h_, l_); g_vh[vb1] = h_;        g_vl[vb1] = l_;        \
            split2(e1, h_, l_); g_vh[vb1 + NSEQ] = h_; g_vl[vb1 + NSEQ] = l_; \
            split2(e2, h_, l_); g_vh[vb2] = h_;        g_vl[vb2] = l_;        \
            split2(e3, h_, l_); g_vh[vb2 + NSEQ] = h_; g_vl[vb2 + NSEQ] = l_; \
        } else {                                                              \
            const float sc_ = (t3 == 0) ? QSCALE : 1.0f;                      \
            __nv_bfloat16* dh = (t3 == 0) ? g_qh : g_kh;                      \
            __nv_bfloat16* dl = (t3 == 0) ? g_ql : g_kl;                      \
            uint32_t hp_, lp_;                                                \
            const size_t i1 = ((((size_t)(s * NB + b1_) * NH + h) * NSEQ + nq1) * DH + d0); \
            const size_t i2 = ((((size_t)(s * NB + b2_) * NH + h) * NSEQ + nq2) * DH + d0); \
            splitpack2(e0 * sc_, e1 * sc_, hp_, lp_);                         \
            *(uint32_t*)(dh + i1) = hp_; *(uint32_t*)(dl + i1) = lp_;         \
            splitpack2(e2 * sc_, e3 * sc_, hp_, lp_);                         \
            *(uint32_t*)(dh + i2) = hp_; *(uint32_t*)(dl + i2) = lp_;         \
        }                                                                     \
    } else {                                                                  \
        const float* bias = s ? bias2 : bias1;                                \
        const float bx = bias[colg], by = bias[colg + 1];                     \
        *(float2*)(out + ((size_t)s * MTOT + row0) * DIM + colg)              \
            = make_float2(e0 + bx, e1 + by);                                  \
        *(float2*)(out + ((size_t)s * MTOT + row0 + 8) * DIM + colg)          \
            = make_float2(e2 + bx, e3 + by);                                  \
    }                                                                         \
} while (0)

#define STAGE_LOAD_A(cc) do {                                                 \
    const float* _p = pA0 + (cc) * KC;                                        \
    _Pragma("unroll")                                                         \
    for (int i4 = 0; i4 < 4; i4++) {                                          \
        float4 v = *(const float4*)(_p + i4 * 4);                             \
        if (mode == 1) {                                                      \
            float4 w = *(const float4*)(pA1 + (cc) * KC + i4 * 4);            \
            v.x += w.x; v.y += w.y; v.z += w.z; v.w += w.w;                   \
        }                                                                     \
        ar[i4 * 4 + 0] = v.x; ar[i4 * 4 + 1] = v.y;                           \
        ar[i4 * 4 + 2] = v.z; ar[i4 * 4 + 3] = v.w;                           \
    }                                                                         \
} while (0)

#define STAGE_LOAD_B(cc) do {                                                 \
    _Pragma("unroll")                                                         \
    for (int p = 0; p < 2; p++) {                                             \
        float4 v = *(const float4*)(pB + ((size_t)(cc) * KC + p * 16) * Ntot);\
        br[p * 4 + 0] = v.x; br[p * 4 + 1] = v.y;                             \
        br[p * 4 + 2] = v.z; br[p * 4 + 3] = v.w;                             \
    }                                                                         \
} while (0)

__global__ void __launch_bounds__(256, 2) hmma_gemm_kernel(
    const float* __restrict__ A1g, const float* __restrict__ A2g,
    const float* __restrict__ B1g, const float* __restrict__ B2g,
    int Ntot, int mode,
    const float* __restrict__ bias1, const float* __restrict__ bias2,
    float* __restrict__ out)
{
    extern __shared__ __align__(16) char smc[];
    const uint32_t sb = s2u(smc);
    const int tid  = threadIdx.x;
    const int lane = tid & 31;
    const int warp = tid >> 5;
    const int wm   = warp >> 1;
    const int wn   = warp & 1;
    const int g    = lane >> 2;
    const int tg   = lane & 3;
    const int s    = blockIdx.z;
    const int m0   = blockIdx.y * 128;
    const int n0   = blockIdx.x * 64;

    const int arow = tid >> 1;
    const int akb  = (tid & 1) * 16;
    const float* pA0;
    const float* pA1 = nullptr;
    if (mode == 0) {
        const float* Ag = s ? A2g : A1g;
        pA0 = Ag + (size_t)(m0 + arow) * KDIM + akb;
    } else {
        const size_t per = (size_t)MTOT * KDIM;
        pA0 = g_attn + (size_t)(2 * s) * per + (size_t)(m0 + arow) * KDIM + akb;
        pA1 = pA0 + per;
    }

    const float* Bg = s ? B2g : B1g;
    const int kkB = tid >> 4;
    const int nnB = (tid & 15) * 4;
    const float* pB = Bg + (size_t)kkB * Ntot + n0 + nnB;

    const uint32_t aA0 = sb + OFF_AH + (uint32_t)((wm * 32 + (lane & 15)) * ROWB + (lane >> 4) * 16);
    const uint32_t aA1 = aA0 + 16 * ROWB;
    const int bro = (lane & 7) + ((lane >> 4) << 3);
    const uint32_t aB0 = sb + OFF_BH + (uint32_t)((wn * 32 + bro) * ROWB + ((lane >> 3) & 1) * 16);
    const uint32_t aB1 = aB0 + 16 * ROWB;

    DECL_ACC(0,0); DECL_ACC(0,1); DECL_ACC(0,2); DECL_ACC(0,3);
    DECL_ACC(1,0); DECL_ACC(1,1); DECL_ACC(1,2); DECL_ACC(1,3);

    float ar[16];
    float br[8];
    STAGE_LOAD_A(0);
    STAGE_LOAD_B(0);

    for (int c = 0; c < NCH; c++) {
        const uint32_t boff = (uint32_t)((c & 1) * STAGEB);
        {
            char* bufp = smc + (c & 1) * STAGEB;
            char* adst = bufp + arow * ROWB + akb * 2;
            #pragma unroll
            for (int i = 0; i < 8; i++) {
                uint32_t hp, lp;
                splitpack2(ar[2 * i], ar[2 * i + 1], hp, lp);
                *(uint32_t*)(adst + OFF_AH + i * 4) = hp;
                *(uint32_t*)(adst + OFF_AL + i * 4) = lp;
            }
            #pragma unroll
            for (int p = 0; p < 2; p++) {
                const int kchunk = kkB + p * 16;
                #pragma unroll
                for (int j = 0; j < 4; j++) {
                    __nv_bfloat16 h, l;
                    split2(br[p * 4 + j], h, l);
                    const int n = nnB + j;
                    *(__nv_bfloat16*)(bufp + OFF_BH + n * ROWB + kchunk * 2) = h;
                    *(__nv_bfloat16*)(bufp + OFF_BL + n * ROWB + kchunk * 2) = l;
                }
            }
        }
        __syncthreads();

        if (c + 1 < NCH) {
            STAGE_LOAD_A(c + 1);
            STAGE_LOAD_B(c + 1);
        }

        #pragma unroll
        for (int kk = 0; kk < 2; kk++) {
            const uint32_t ko = boff + kk * 32;
            uint32_t bh00, bh01, bh10, bh11, bl00, bl01, bl10, bl11;
            uint32_t bh20, bh21, bh30, bh31, bl20, bl21, bl30, bl31;
            LDSM4(bh00, bh01, bh10, bh11, aB0 + ko);
            LDSM4(bl00, bl01, bl10, bl11, aB0 + ko + 5120);
            LDSM4(bh20, bh21, bh30, bh31, aB1 + ko);
            LDSM4(bl20, bl21, bl30, bl31, aB1 + ko + 5120);
            {
                uint32_t ah0, ah1, ah2, ah3, al0, al1, al2, al3;
                LDSM4(ah0, ah1, ah2, ah3, aA0 + ko);
                LDSM4(al0, al1, al2, al3, aA0 + ko + OFF_AL);
                MMA3(0,0); MMA3(0,1); MMA3(0,2); MMA3(0,3);
            }
            {
                uint32_t ah0, ah1, ah2, ah3, al0, al1, al2, al3;
                LDSM4(ah0, ah1, ah2, ah3, aA1 + ko);
                LDSM4(al0, al1, al2, al3, aA1 + ko + OFF_AL);
                MMA3(1,0); MMA3(1,1); MMA3(1,2); MMA3(1,3);
            }
        }
    }

    EPILOG(0,0); EPILOG(0,1); EPILOG(0,2); EPILOG(0,3);
    EPILOG(1,0); EPILOG(1,1); EPILOG(1,2); EPILOG(1,3);
}

// ============================ HMMA attention ================================
#define AROWB  144
#define A_VOFF (2*64*AROWB)         // 18432
#define A_LOFF (64*AROWB)           // 9216
#define ATT_SMEM (4*64*AROWB)       // 36864
#define ATT_SMEM2 (2*ATT_SMEM)      // 73728

#define LOADQ(ks)                                                             \
    uint32_t qh##ks##0, qh##ks##1, qh##ks##2, qh##ks##3;                      \
    uint32_t ql##ks##0, ql##ks##1, ql##ks##2, ql##ks##3;                      \
    do {                                                                      \
        qh##ks##0 = *(const uint32_t*)(Qh0 + (ks)*16 + 2*tg);                 \
        qh##ks##1 = *(const uint32_t*)(Qh1 + (ks)*16 + 2*tg);                 \
        qh##ks##2 = *(const uint32_t*)(Qh0 + (ks)*16 + 8 + 2*tg);             \
        qh##ks##3 = *(const uint32_t*)(Qh1 + (ks)*16 + 8 + 2*tg);             \
        ql##ks##0 = *(const uint32_t*)(Ql0 + (ks)*16 + 2*tg);                 \
        ql##ks##1 = *(const uint32_t*)(Ql1 + (ks)*16 + 2*tg);                 \
        ql##ks##2 = *(const uint32_t*)(Ql0 + (ks)*16 + 8 + 2*tg);             \
        ql##ks##3 = *(const uint32_t*)(Ql1 + (ks)*16 + 8 + 2*tg);             \
    } while (0)

#define ADECL_S(nt) float s##nt##0=0.f, s##nt##1=0.f, s##nt##2=0.f, s##nt##3=0.f
#define ADECL_O(nt) float o##nt##0=0.f, o##nt##1=0.f, o##nt##2=0.f, o##nt##3=0.f
#define ADECL_P(nt) uint32_t pha##nt=0u, phb##nt=0u, pla##nt=0u, plb##nt=0u

#define ASMMA_P(ks,p,na,nb) do {                                              \
    uint32_t kh0,kh1,kh2,kh3, kl0,kl1,kl2,kl3;                                \
    LDSM4(kh0,kh1,kh2,kh3, aK##p + abuf + (ks)*32);                           \
    LDSM4(kl0,kl1,kl2,kl3, aK##p + abuf + A_LOFF + (ks)*32);                  \
    MMA16816(s##na##0,s##na##1,s##na##2,s##na##3,                             \
             qh##ks##0,qh##ks##1,qh##ks##2,qh##ks##3, kh0,kh1);               \
    MMA16816(s##na##0,s##na##1,s##na##2,s##na##3,                             \
             qh##ks##0,qh##ks##1,qh##ks##2,qh##ks##3, kl0,kl1);               \
    MMA16816(s##na##0,s##na##1,s##na##2,s##na##3,                             \
             ql##ks##0,ql##ks##1,ql##ks##2,ql##ks##3, kh0,kh1);               \
    MMA16816(s##nb##0,s##nb##1,s##nb##2,s##nb##3,                             \
             qh##ks##0,qh##ks##1,qh##ks##2,qh##ks##3, kh2,kh3);               \
    MMA16816(s##nb##0,s##nb##1,s##nb##2,s##nb##3,                             \
             qh##ks##0,qh##ks##1,qh##ks##2,qh##ks##3, kl2,kl3);               \
    MMA16816(s##nb##0,s##nb##1,s##nb##2,s##nb##3,                             \
             ql##ks##0,ql##ks##1,ql##ks##2,ql##ks##3, kh2,kh3);               \
} while (0)

#define ASMMA_ALLNT(ks) do {                                                  \
    ASMMA_P(ks,0,0,1); ASMMA_P(ks,1,2,3);                                     \
    ASMMA_P(ks,2,4,5); ASMMA_P(ks,3,6,7); } while (0)

#define AROWMAX(nt) do {                                                      \
    mxA = fmaxf(mxA, fmaxf(s##nt##0, s##nt##1));                              \
    mxB = fmaxf(mxB, fmaxf(s##nt##2, s##nt##3)); } while (0)

#define ASOFT(nt) do {                                                        \
    const float p0_ = fexp(s##nt##0 - mxA);                                   \
    const float p1_ = fexp(s##nt##1 - mxA);                                   \
    const float p2_ = fexp(s##nt##2 - mxB);                                   \
    const float p3_ = fexp(s##nt##3 - mxB);                                   \
    sumA += p0_ + p1_; sumB += p2_ + p3_;                                     \
    splitpack2(p0_, p1_, pha##nt, pla##nt);                                   \
    splitpack2(p2_, p3_, phb##nt, plb##nt);                                   \
    o##nt##0 *= corrA; o##nt##1 *= corrA;                                     \
    o##nt##2 *= corrB; o##nt##3 *= corrB; } while (0)

#define APV_P(ks,ta,tb,p,na,nb) do {                                          \
    uint32_t vh0,vh1,vh2,vh3, vl0,vl1,vl2,vl3;                                \
    LDSM4(vh0,vh1,vh2,vh3, aV##p + abuf + (ks)*32);                           \
    LDSM4(vl0,vl1,vl2,vl3, aV##p + abuf + A_LOFF + (ks)*32);                  \
    MMA16816(o##na##0,o##na##1,o##na##2,o##na##3,                             \
             pha##ta, phb##ta, pha##tb, phb##tb, vh0,vh1);                    \
    MMA16816(o##na##0,o##na##1,o##na##2,o##na##3,                             \
             pha##ta, phb##ta, pha##tb, phb##tb, vl0,vl1);                    \
    MMA16816(o##na##0,o##na##1,o##na##2,o##na##3,                             \
             pla##ta, plb##ta, pla##tb, plb##tb, vh0,vh1);                    \
    MMA16816(o##nb##0,o##nb##1,o##nb##2,o##nb##3,                             \
             pha##ta, phb##ta, pha##tb, phb##tb, vh2,vh3);                    \
    MMA16816(o##nb##0,o##nb##1,o##nb##2,o##nb##3,                             \
             pha##ta, phb##ta, pha##tb, phb##tb, vl2,vl3);                    \
    MMA16816(o##nb##0,o##nb##1,o##nb##2,o##nb##3,                             \
             pla##ta, plb##ta, pla##tb, plb##tb, vh2,vh3);                    \
} while (0)

#define APVMMA_ALLNT(ks,ta,tb) do {                                           \
    APV_P(ks,ta,tb,0,0,1); APV_P(ks,ta,tb,1,2,3);                             \
    APV_P(ks,ta,tb,2,4,5); APV_P(ks,ta,tb,3,6,7); } while (0)

#define AWRITE(nt) do {                                                       \
    *(float2*)(OgA + (nt)*8 + 2*tg) = make_float2(o##nt##0*invA, o##nt##1*invA); \
    *(float2*)(OgB + (nt)*8 + 2*tg) = make_float2(o##nt##2*invB, o##nt##3*invB); \
} while (0)

__global__ void __launch_bounds__(256, 1) attn_hmma_kernel()
{
    extern __shared__ __align__(16) char smc[];
    const uint32_t sb = s2u(smc);
    const int tid  = threadIdx.x;
    const int lane = tid & 31;
    const int warp = tid >> 5;
    const int g    = lane >> 2;
    const int tg   = lane & 3;
    const int combo = blockIdx.z;
    const int bh    = blockIdx.y;
    const int q0    = blockIdx.x * 128;
    const int qs    = combo >> 1;
    const int kvs   = ((combo + 1) >> 1) & 1;

    const size_t qoff  = ((size_t)(qs  * NB * NH) + bh) * NSEQ * DH;
    const size_t kvoff = ((size_t)(kvs * NB * NH) + bh) * NSEQ * DH;

    const __nv_bfloat16* Qh0 = g_qh + qoff + (size_t)(q0 + warp * 16 + g) * DH;
    const __nv_bfloat16* Qh1 = Qh0 + 8 * DH;
    const __nv_bfloat16* Ql0 = g_ql + qoff + (size_t)(q0 + warp * 16 + g) * DH;
    const __nv_bfloat16* Ql1 = Ql0 + 8 * DH;
    LOADQ(0); LOADQ(1); LOADQ(2); LOADQ(3);

    ADECL_O(0); ADECL_O(1); ADECL_O(2); ADECL_O(3);
    ADECL_O(4); ADECL_O(5); ADECL_O(6); ADECL_O(7);
    float mA = -1e30f, mB = -1e30f, lA = 0.f, lB = 0.f;

    // staging maps: thread -> row (key for K, d for V), 16-elem segment
    const int srow = tid >> 2;
    const int sel  = (tid & 3) * 16;
    const __nv_bfloat16* pKh = g_kh + kvoff + (size_t)srow * DH + sel;
    const __nv_bfloat16* pKl = g_kl + kvoff + (size_t)srow * DH + sel;
    const __nv_bfloat16* pVh = g_vh + kvoff + (size_t)srow * NSEQ + sel;
    const __nv_bfloat16* pVl = g_vl + kvoff + (size_t)srow * NSEQ + sel;
    char* kds = smc + srow * AROWB + sel * 2;
    char* vds = smc + A_VOFF + srow * AROWB + sel * 2;

    // per-lane ldmatrix base addresses
    const int bro = (lane & 7) + ((lane >> 4) << 3);
    const uint32_t kb16 = ((lane >> 3) & 1) * 16;
    const uint32_t aK0 = sb + (uint32_t)(bro * AROWB) + kb16;
    const uint32_t aK1 = aK0 + 16 * AROWB;
    const uint32_t aK2 = aK0 + 32 * AROWB;
    const uint32_t aK3 = aK0 + 48 * AROWB;
    const uint32_t aV0 = aK0 + A_VOFF;
    const uint32_t aV1 = aK1 + A_VOFF;
    const uint32_t aV2 = aK2 + A_VOFF;
    const uint32_t aV3 = aK3 + A_VOFF;

    for (int kt = 0; kt < NSEQ / 64; kt++) {
        const int k0 = kt * 64;
        const int ab = (kt & 1) * ATT_SMEM;
        // pure-copy staging: K rows advance by k0*DH, V columns by k0
        {
            const size_t ko_k = (size_t)k0 * DH;
            uint4 t0 = *(const uint4*)(pKh + ko_k);
            uint4 t1 = *(const uint4*)(pKh + ko_k + 8);
            *(uint4*)(kds + ab)      = t0;
            *(uint4*)(kds + ab + 16) = t1;
            t0 = *(const uint4*)(pKl + ko_k);
            t1 = *(const uint4*)(pKl + ko_k + 8);
            *(uint4*)(kds + ab + A_LOFF)      = t0;
            *(uint4*)(kds + ab + A_LOFF + 16) = t1;
            t0 = *(const uint4*)(pVh + k0);
            t1 = *(const uint4*)(pVh + k0 + 8);
            *(uint4*)(vds + ab)      = t0;
            *(uint4*)(vds + ab + 16) = t1;
            t0 = *(const uint4*)(pVl + k0);
            t1 = *(const uint4*)(pVl + k0 + 8);
            *(uint4*)(vds + ab + A_LOFF)      = t0;
            *(uint4*)(vds + ab + A_LOFF + 16) = t1;
        }
        __syncthreads();
        const uint32_t abuf = (uint32_t)ab;

        // S = Q K^T
        ADECL_S(0); ADECL_S(1); ADECL_S(2); ADECL_S(3);
        ADECL_S(4); ADECL_S(5); ADECL_S(6); ADECL_S(7);
        ASMMA_ALLNT(0); ASMMA_ALLNT(1); ASMMA_ALLNT(2); ASMMA_ALLNT(3);

        // online softmax
        float mxA = mA, mxB = mB;
        AROWMAX(0); AROWMAX(1); AROWMAX(2); AROWMAX(3);
        AROWMAX(4); AROWMAX(5); AROWMAX(6); AROWMAX(7);
        mxA = fmaxf(mxA, __shfl_xor_sync(0xffffffffu, mxA, 1));
        mxA = fmaxf(mxA, __shfl_xor_sync(0xffffffffu, mxA, 2));
        mxB = fmaxf(mxB, __shfl_xor_sync(0xffffffffu, mxB, 1));
        mxB = fmaxf(mxB, __shfl_xor_sync(0xffffffffu, mxB, 2));
        const float corrA = fexp(mA - mxA);
        const float corrB = fexp(mB - mxB);
        float sumA = 0.f, sumB = 0.f;
        ADECL_P(0); ADECL_P(1); ADECL_P(2); ADECL_P(3);
        ADECL_P(4); ADECL_P(5); ADECL_P(6); ADECL_P(7);
        ASOFT(0); ASOFT(1); ASOFT(2); ASOFT(3);
        ASOFT(4); ASOFT(5); ASOFT(6); ASOFT(7);
        sumA += __shfl_xor_sync(0xffffffffu, sumA, 1);
        sumA += __shfl_xor_sync(0xffffffffu, sumA, 2);
        sumB += __shfl_xor_sync(0xffffffffu, sumB, 1);
        sumB += __shfl_xor_sync(0xffffffffu, sumB, 2);
        lA = lA * corrA + sumA;
        lB = lB * corrB + sumB;
        mA = mxA; mB = mxB;

        // O += P V
        APVMMA_ALLNT(0,0,1); APVMMA_ALLNT(1,2,3);
        APVMMA_ALLNT(2,4,5); APVMMA_ALLNT(3,6,7);
    }

    const int b = bh / NH, h = bh - (bh / NH) * NH;
    const int row0 = q0 + warp * 16 + g;
    float* OgA = g_attn + ((size_t)(combo * NB + b) * NSEQ + row0) * DIM + h * DH;
    float* OgB = OgA + 8 * DIM;
    const float invA = 1.f / lA, invB = 1.f / lB;
    AWRITE(0); AWRITE(1); AWRITE(2); AWRITE(3);
    AWRITE(4); AWRITE(5); AWRITE(6); AWRITE(7);
}

// ============================ launch ========================================
extern "C" void kernel_launch(void* const* d_in, const int* in_sizes, int n_in,
                              void* d_out, int out_size)
{
    const float* x1    = (const float*)d_in[0];
    const float* x2    = (const float*)d_in[1];
    const float* Wqkv1 = (const float*)d_in[2];
    const float* Wqkv2 = (const float*)d_in[3];
    const float* Wp1   = (const float*)d_in[4];
    const float* bp1   = (const float*)d_in[5];
    const float* Wp2   = (const float*)d_in[6];
    const float* bp2   = (const float*)d_in[7];
    float* out = (float*)d_out;

    cudaFuncSetAttribute(hmma_gemm_kernel,
                         cudaFuncAttributeMaxDynamicSharedMemorySize, GEMM_SMEM);
    cudaFuncSetAttribute(attn_hmma_kernel,
                         cudaFuncAttributeMaxDynamicSharedMemorySize, ATT_SMEM2);

    hmma_gemm_kernel<<<dim3(NQKV / 64, MTOT / 128, 2), 256, GEMM_SMEM>>>(
        x1, x2, Wqkv1, Wqkv2, NQKV, 0, nullptr, nullptr, nullptr);

    attn_hmma_kernel<<<dim3(8, 24, 4), 256, ATT_SMEM2>>>();

    hmma_gemm_kernel<<<dim3(DIM / 64, MTOT / 128, 2), 256, GEMM_SMEM>>>(
        nullptr, nullptr, Wp1, Wp2, DIM, 1, bp1, bp2, out);
}